// round 5
// baseline (speedup 1.0000x reference)
#include <cuda_runtime.h>

#define E     1024
#define LAY   24
#define HID   4096
#define VOCAB 50277
#define NBLK  148
#define NTHR  512
#define NWARP (NTHR / 32)
#define GWARPS (NBLK * NWARP)   // 2368
#define GSTRIDE (NBLK * NTHR)

// ---------------- scratch (device globals: no allocations allowed) ----------
__device__ __align__(16) float g_x[E];
__device__ __align__(16) float g_r[E];
__device__ __align__(16) float g_k[E];
__device__ __align__(16) float g_v[E];
__device__ __align__(16) float g_rf[E];
__device__ __align__(16) float g_kf[HID];
__device__ unsigned g_leaf[8] = {0,0,0,0,0,0,0,0};
__device__ unsigned g_root = 0;
__device__ unsigned g_flag[8 * 32];   // one release flag per bucket, 128B apart

struct Params {
    const int*   ctx;
    const float *xx_att, *aa_att, *bb_att, *pp_att, *xx_ffn;
    const float *emb_w, *head_w;
    const float *ln0_w, *ln0_b, *ln1_w, *ln1_b, *ln2_w, *ln2_b, *lno_w, *lno_b;
    const float *mk, *mv, *mr, *tf, *td;
    const float *Wr, *Wk, *Wv, *Wo;
    const float *fmk, *fmr, *Fr, *Fk, *Fv;
    float* out;
};

// ---------------- acquire/release primitives --------------------------------
__device__ __forceinline__ unsigned ld_acq(const unsigned* p) {
    unsigned v;
    asm volatile("ld.acquire.gpu.global.u32 %0, [%1];" : "=r"(v) : "l"(p));
    return v;
}
__device__ __forceinline__ void st_rel(unsigned* p, unsigned v) {
    asm volatile("st.release.gpu.global.u32 [%0], %1;" :: "l"(p), "r"(v));
}
__device__ __forceinline__ unsigned atom_add_ar(unsigned* p, unsigned v) {
    unsigned old;
    asm volatile("atom.acq_rel.gpu.global.add.u32 %0, [%1], %2;"
                 : "=r"(old) : "l"(p), "r"(v));
    return old;
}

// ------------- two-level grid barrier, acq_rel, bucketed release flags ------
__device__ __forceinline__ void grid_sync() {
    __syncthreads();
    if (threadIdx.x == 0) {
        const int b = blockIdx.x & 7;
        unsigned* flag = &g_flag[b * 32];
        const unsigned gen = ld_acq(flag);
        const unsigned cnt = 18u + (b < 4 ? 1u : 0u);   // 148 = 4*19 + 4*18
        if (atom_add_ar(&g_leaf[b], 1u) == cnt - 1u) {
            atomicExch(&g_leaf[b], 0u);
            if (atom_add_ar(&g_root, 1u) == 7u) {
                atomicExch(&g_root, 0u);
                #pragma unroll
                for (int i = 0; i < 8; i++) st_rel(&g_flag[i * 32], gen + 1u);
            } else {
                while ((int)(ld_acq(flag) - gen) <= 0) __nanosleep(32);
            }
        } else {
            while ((int)(ld_acq(flag) - gen) <= 0) __nanosleep(32);
        }
    }
    __syncthreads();
}

// ---------------- L2 prefetch stream (grid-strided, 128B lines) -------------
__device__ __forceinline__ void pfl2(const float* p, unsigned nfloats, unsigned gt) {
    const char* c = (const char*)p;
    const unsigned nlines = nfloats >> 5;
    for (unsigned i = gt; i < nlines; i += GSTRIDE)
        asm volatile("prefetch.global.L2 [%0];" :: "l"(c + (size_t)i * 128u));
}

// ---------------- block reduction (sum, broadcast) ---------------------------
__device__ __forceinline__ float block_sum(float v, float* red) {
    #pragma unroll
    for (int o = 16; o; o >>= 1) v += __shfl_xor_sync(0xffffffffu, v, o);
    int w = threadIdx.x >> 5;
    if ((threadIdx.x & 31) == 0) red[w] = v;
    __syncthreads();
    if (threadIdx.x < 32) {
        float t = (threadIdx.x < NWARP) ? red[threadIdx.x] : 0.f;
        #pragma unroll
        for (int o = 16; o; o >>= 1) t += __shfl_xor_sync(0xffffffffu, t, o);
        if (threadIdx.x == 0) red[0] = t;
    }
    __syncthreads();
    float r = red[0];
    __syncthreads();
    return r;
}

// two-pass LayerNorm: src (global) -> dst (shared), per-block redundant
__device__ void block_ln(const float* __restrict__ src,
                         const float* __restrict__ w,
                         const float* __restrict__ b,
                         float* dst, float* red) {
    float s = 0.f;
    for (int j = threadIdx.x; j < E; j += NTHR) { float t = src[j]; dst[j] = t; s += t; }
    float mean = block_sum(s, red) * (1.f / E);
    float s2 = 0.f;
    for (int j = threadIdx.x; j < E; j += NTHR) { float c = dst[j] - mean; s2 += c * c; }
    float inv = rsqrtf(block_sum(s2, red) * (1.f / E) + 1e-5f);
    for (int j = threadIdx.x; j < E; j += NTHR)
        dst[j] = (dst[j] - mean) * inv * w[j] + b[j];
    __syncthreads();
}

// ---------------- GEMV pieces ------------------------------------------------
__device__ __forceinline__ float red32(float s) {
    #pragma unroll
    for (int o = 16; o; o >>= 1) s += __shfl_xor_sync(0xffffffffu, s, o);
    return s;
}

__device__ __forceinline__ void pf8(const float* __restrict__ Wrow, int lane,
                                    float4 (&a)[8]) {
    const float4* W = (const float4*)Wrow;
    #pragma unroll
    for (int t = 0; t < 8; t++) a[t] = W[lane + 32 * t];
}

__device__ __forceinline__ float dot8_pf(const float4 (&a)[8],
                                         const float* __restrict__ vec, int lane) {
    const float4* v = (const float4*)vec;
    float s = 0.f;
    #pragma unroll
    for (int t = 0; t < 8; t++) {
        float4 x = v[lane + 32 * t];
        s = fmaf(a[t].x, x.x, s); s = fmaf(a[t].y, x.y, s);
        s = fmaf(a[t].z, x.z, s); s = fmaf(a[t].w, x.w, s);
    }
    return red32(s);
}

__device__ __forceinline__ float warp_dot8(const float* __restrict__ Wrow,
                                           const float* __restrict__ vec, int lane) {
    float4 a[8];
    pf8(Wrow, lane, a);
    return dot8_pf(a, vec, lane);
}

// 4096-long row: chunk0 prefetched in a[], chunks 1..3 double-buffered
__device__ __forceinline__ float dot32_pf(float4 (&a)[8],
                                          const float* __restrict__ Wrow,
                                          const float* __restrict__ vec, int lane) {
    const float4* W = (const float4*)Wrow;
    const float4* v = (const float4*)vec;
    float4 b[8];
    float s = 0.f;
    #pragma unroll
    for (int c = 0; c < 4; c++) {
        if (c < 3) {
            #pragma unroll
            for (int t = 0; t < 8; t++) b[t] = W[lane + 32 * t + 256 * (c + 1)];
        }
        #pragma unroll
        for (int t = 0; t < 8; t++) {
            float4 x = v[lane + 32 * t + 256 * c];
            s = fmaf(a[t].x, x.x, s); s = fmaf(a[t].y, x.y, s);
            s = fmaf(a[t].z, x.z, s); s = fmaf(a[t].w, x.w, s);
        }
        #pragma unroll
        for (int t = 0; t < 8; t++) a[t] = b[t];
    }
    return red32(s);
}

__device__ __forceinline__ float sigmoidf_(float x) {
    return 1.f / (1.f + expf(-x));
}

// phase-A row -> weight pointer (rows 0..1023:Wr, 1024..2047:Wk, 2048..3071:Wv)
__device__ __forceinline__ const float* wrowA(const Params& p, int l, int row) {
    int m = row >> 10, i = row & (E - 1);
    const float* Wb = (m == 0) ? p.Wr : (m == 1) ? p.Wk : p.Wv;
    return Wb + (size_t)l * E * E + (size_t)i * E;
}

// ---------------- the whole network in one persistent kernel ----------------
__global__ void __launch_bounds__(NTHR, 1) rwkv_kernel(Params p) {
    __shared__ __align__(16) float sh[HID];   // 16KB, aliased per phase
    __shared__ float red[NWARP];

    const int tid  = threadIdx.x;
    const int gw   = blockIdx.x * NWARP + (tid >> 5);
    const int lane = tid & 31;
    const unsigned gt = blockIdx.x * NTHR + tid;

    float* outv  = p.out;                 // logits [V]
    float* o_xx  = p.out + VOCAB;         // xx_att_r [L,E]
    float* o_aa  = o_xx  + LAY * E;
    float* o_bb  = o_aa  + LAY * E;
    float* o_pp  = o_bb  + LAY * E;
    float* o_xxf = o_pp  + LAY * E;
    float* o_da  = o_xxf + LAY * E;       // r_pre
    float* o_db  = o_da  + LAY * E;       // sigmoid(r_pre)

    float4 a[8];                          // cross-barrier register prefetch

    // ---- init: L2-prefetch layer-0 A+B weights, then x0 = LN(emb, ln0) ----
    pfl2(p.Wr, E * E, gt);
    pfl2(p.Wk, E * E, gt);
    pfl2(p.Wv, E * E, gt);
    pfl2(p.Wo, E * E, gt);
    pfl2(p.ln1_w, E, gt); pfl2(p.ln1_b, E, gt);
    pfl2(p.xx_att, E, gt);
    pfl2(p.mk, E, gt); pfl2(p.mv, E, gt); pfl2(p.mr, E, gt);
    {
        int tok = p.ctx[0];
        block_ln(p.emb_w + (size_t)tok * E, p.ln0_w, p.ln0_b, sh, red);
        if (blockIdx.x == 0)
            for (int j = tid; j < E; j += NTHR) g_x[j] = sh[j];
    }
    pf8(wrowA(p, 0, gw), lane, a);
    grid_sync();

    for (int l = 0; l < LAY; l++) {
        const size_t lE  = (size_t)l * E;
        const size_t lEE = (size_t)l * E * E;
        const size_t lHE = (size_t)l * HID * E;
        const size_t lEH = (size_t)l * E * HID;

        // ================= Phase A: LN1 + mixes + r/k/v GEMVs ==============
        // prefetch phase-C big array + phase-B params
        pfl2(p.Fk + lHE, HID * E, gt);
        pfl2(p.aa_att + lE, E, gt); pfl2(p.bb_att + lE, E, gt);
        pfl2(p.pp_att + lE, E, gt);
        pfl2(p.tf + lE, E, gt); pfl2(p.td + lE, E, gt);

        float* xn = sh; float* xk = sh + E; float* xv = sh + 2 * E; float* xr = sh + 3 * E;
        block_ln(g_x, p.ln1_w + lE, p.ln1_b + lE, xn, red);
        for (int j = tid; j < E; j += NTHR) {
            float xnj = xn[j], sx = p.xx_att[lE + j];
            float ak = p.mk[lE + j], bv = p.mv[lE + j], cr = p.mr[lE + j];
            xk[j] = xnj * ak + sx * (1.f - ak);
            xv[j] = xnj * bv + sx * (1.f - bv);
            xr[j] = xnj * cr + sx * (1.f - cr);
            if (blockIdx.x == 0) o_xx[lE + j] = xnj;
        }
        __syncthreads();
        {
            int m = gw >> 10, i = gw & (E - 1);
            const float* vec = (m == 0) ? xr : (m == 1) ? xk : xv;
            float s = dot8_pf(a, vec, lane);
            if (lane == 0) ((m == 0) ? g_r : (m == 1) ? g_k : g_v)[i] = s;
        }
        for (int row = gw + GWARPS; row < 3 * E; row += GWARPS) {
            int m = row >> 10, i = row & (E - 1);
            const float* vec = (m == 0) ? xr : (m == 1) ? xk : xv;
            float s = warp_dot8(wrowA(p, l, row), vec, lane);
            if (lane == 0) ((m == 0) ? g_r : (m == 1) ? g_k : g_v)[i] = s;
        }
        if (gw < E) pf8(p.Wo + lEE + (size_t)gw * E, lane, a);   // phase-B row
        grid_sync();

        // ================= Phase B: WKV elementwise + Wo GEMV ==============
        // prefetch phase-C small GEMV + phase-D big array + phase-C params
        pfl2(p.Fr + lEE, E * E, gt);
        pfl2(p.Fv + lEH, E * HID, gt);
        pfl2(p.ln2_w + lE, E, gt); pfl2(p.ln2_b + lE, E, gt);
        pfl2(p.xx_ffn + lE, E, gt);
        pfl2(p.fmk + lE, E, gt); pfl2(p.fmr + lE, E, gt);

        float* oin = sh;
        for (int j = tid; j < E; j += NTHR) {
            float kj = g_k[j], vj = g_v[j], rp = g_r[j];
            float aa = p.aa_att[lE + j], bb = p.bb_att[lE + j], pp = p.pp_att[lE + j];
            float tf = p.tf[lE + j],     td = p.td[lE + j];
            float ww = tf + kj;
            float q  = fmaxf(pp, ww);
            float e1 = expf(pp - q), e2 = expf(ww - q);
            float av = e1 * aa + e2 * vj;
            float bv = e1 * bb + e2;
            float rr = sigmoidf_(rp);
            oin[j] = rr * av / bv;
            if (blockIdx.x == 0) {
                float ww2 = pp + td;
                float q2  = fmaxf(ww2, kj);
                float f1  = expf(ww2 - q2), f2 = expf(kj - q2);
                o_aa[lE + j] = f1 * aa + f2 * vj;
                o_bb[lE + j] = f1 * bb + f2;
                o_pp[lE + j] = q2;
                o_da[lE + j] = rp;
                o_db[lE + j] = rr;
            }
        }
        __syncthreads();
        if (gw < E) {
            float s = dot8_pf(a, oin, lane);
            if (lane == 0) g_x[gw] += s;
        }
        pf8(p.Fk + lHE + (size_t)gw * E, lane, a);               // phase-C row
        grid_sync();

        // ================= Phase C: LN2 + mixes + Fk/Fr GEMVs ==============
        // prefetch next layer's phase-A weights (or head chunk 0)
        if (l + 1 < LAY) {
            pfl2(p.Wr + lEE + E * E, E * E, gt);
            pfl2(p.Wk + lEE + E * E, E * E, gt);
            pfl2(p.Wv + lEE + E * E, E * E, gt);
        } else {
            pfl2(p.head_w, 4 * 1024 * 1024, gt);                 // head 16MB
        }

        float* xn2 = sh; float* fxk = sh + E; float* fxr = sh + 2 * E;
        block_ln(g_x, p.ln2_w + lE, p.ln2_b + lE, xn2, red);
        for (int j = tid; j < E; j += NTHR) {
            float v = xn2[j], sxf = p.xx_ffn[lE + j];
            float ak = p.fmk[lE + j], br = p.fmr[lE + j];
            fxk[j] = v * ak + sxf * (1.f - ak);
            fxr[j] = v * br + sxf * (1.f - br);
            if (blockIdx.x == 0) o_xxf[lE + j] = v;
        }
        __syncthreads();
        {
            float s = dot8_pf(a, fxk, lane);
            s = fmaxf(s, 0.f);
            if (lane == 0) g_kf[gw] = s * s;
        }
        for (int row = gw + GWARPS; row < HID + E; row += GWARPS) {
            if (row < HID) {
                float s = warp_dot8(p.Fk + lHE + (size_t)row * E, fxk, lane);
                s = fmaxf(s, 0.f);
                if (lane == 0) g_kf[row] = s * s;
            } else {
                int i = row - HID;
                float s = warp_dot8(p.Fr + lEE + (size_t)i * E, fxr, lane);
                if (lane == 0) g_rf[i] = sigmoidf_(s);
            }
        }
        if (gw < E) pf8(p.Fv + lEH + (size_t)gw * HID, lane, a); // phase-D chunk0
        grid_sync();

        // ================= Phase D: Fv GEMV + residual add =================
        // prefetch next layer's Wo + A-phase params (or head chunk 1)
        if (l + 1 < LAY) {
            pfl2(p.Wo + lEE + E * E, E * E, gt);
            pfl2(p.ln1_w + lE + E, E, gt); pfl2(p.ln1_b + lE + E, E, gt);
            pfl2(p.xx_att + lE + E, E, gt);
            pfl2(p.mk + lE + E, E, gt); pfl2(p.mv + lE + E, E, gt);
            pfl2(p.mr + lE + E, E, gt);
        } else {
            pfl2(p.head_w + 4 * 1024 * 1024, 4 * 1024 * 1024, gt);
            pfl2(p.lno_w, E, gt); pfl2(p.lno_b, E, gt);
        }
        {
            const float4* kf4 = (const float4*)g_kf;
            float4* sh4 = (float4*)sh;
            for (int j = tid; j < HID / 4; j += NTHR) sh4[j] = kf4[j];
        }
        __syncthreads();
        if (gw < E) {
            float s = dot32_pf(a, p.Fv + lEH + (size_t)gw * HID, sh, lane);
            if (lane == 0) g_x[gw] += g_rf[gw] * s;
        }
        if (l + 1 < LAY) pf8(wrowA(p, l + 1, gw), lane, a);
        else             pf8(p.head_w + (size_t)gw * E, lane, a);
        grid_sync();
    }

    // ================= head: LN + [V,E] GEMV (ping-pong) ===================
    block_ln(g_x, p.lno_w, p.lno_b, sh, red);
    {
        float4 b[8];
        int row = gw;
        if (row + GWARPS < VOCAB) pf8(p.head_w + (size_t)(row + GWARPS) * E, lane, b);
        while (true) {
            float s = dot8_pf(a, sh, lane);
            if (lane == 0) outv[row] = s;
            int rn = row + GWARPS;
            if (rn >= VOCAB) break;
            int rp = row + 2 * GWARPS;
            if (rp < VOCAB) pf8(p.head_w + (size_t)rp * E, lane, a);
            s = dot8_pf(b, sh, lane);
            if (lane == 0) outv[rn] = s;
            row = rp;
            if (row >= VOCAB) break;
            int rq = rn + 2 * GWARPS;
            if (rq < VOCAB) pf8(p.head_w + (size_t)rq * E, lane, b);
        }
    }
}

extern "C" void kernel_launch(void* const* d_in, const int* in_sizes, int n_in,
                              void* d_out, int out_size) {
    Params p;
    p.ctx    = (const int*)  d_in[0];
    p.xx_att = (const float*)d_in[1];
    p.aa_att = (const float*)d_in[2];
    p.bb_att = (const float*)d_in[3];
    p.pp_att = (const float*)d_in[4];
    p.xx_ffn = (const float*)d_in[5];
    p.emb_w  = (const float*)d_in[6];
    p.head_w = (const float*)d_in[7];
    p.ln0_w  = (const float*)d_in[8];
    p.ln0_b  = (const float*)d_in[9];
    p.ln1_w  = (const float*)d_in[10];
    p.ln1_b  = (const float*)d_in[11];
    p.ln2_w  = (const float*)d_in[12];
    p.ln2_b  = (const float*)d_in[13];
    p.lno_w  = (const float*)d_in[14];
    p.lno_b  = (const float*)d_in[15];
    p.mk     = (const float*)d_in[16];
    p.mv     = (const float*)d_in[17];
    p.mr     = (const float*)d_in[18];
    p.tf     = (const float*)d_in[19];
    p.td     = (const float*)d_in[20];
    p.Wr     = (const float*)d_in[21];
    p.Wk     = (const float*)d_in[22];
    p.Wv     = (const float*)d_in[23];
    p.Wo     = (const float*)d_in[24];
    p.fmk    = (const float*)d_in[25];
    p.fmr    = (const float*)d_in[26];
    p.Fr     = (const float*)d_in[27];
    p.Fk     = (const float*)d_in[28];
    p.Fv     = (const float*)d_in[29];
    p.out    = (float*)d_out;

    rwkv_kernel<<<NBLK, NTHR>>>(p);
}

// round 6
// speedup vs baseline: 1.0050x; 1.0050x over previous
#include <cuda_runtime.h>

#define E     1024
#define LAY   24
#define HID   4096
#define VOCAB 50277
#define NBLK  148
#define NTHR  512
#define CWARP 12
#define CTHR  (CWARP * 32)        // 384 compute threads
#define GW_C  (NBLK * CWARP)      // 1776 compute warps
#define LWARP 4
#define LW_TOT (NBLK * LWARP)     // 592 loader warps
#define NWALL (NTHR / 32)         // 16
#define GW_H  (NBLK * NWALL)      // 2368 head warps

// ---------------- scratch (device globals: no allocations allowed) ----------
__device__ __align__(16) float g_x[E];
__device__ __align__(16) float g_r[E];
__device__ __align__(16) float g_k[E];
__device__ __align__(16) float g_v[E];
__device__ __align__(16) float g_rf[E];
__device__ __align__(16) float g_kf[HID];
__device__ float g_sink;
__device__ unsigned g_bar_leaf[8] = {0,0,0,0,0,0,0,0};
__device__ unsigned g_bar_root = 0;
__device__ volatile unsigned g_bar_gen = 0;

struct Params {
    const int*   ctx;
    const float *xx_att, *aa_att, *bb_att, *pp_att, *xx_ffn;
    const float *emb_w, *head_w;
    const float *ln0_w, *ln0_b, *ln1_w, *ln1_b, *ln2_w, *ln2_b, *lno_w, *lno_b;
    const float *mk, *mv, *mr, *tf, *td;
    const float *Wr, *Wk, *Wv, *Wo;
    const float *fmk, *fmr, *Fr, *Fk, *Fv;
    float* out;
};

// ------------- two-level software grid barrier (R3-proven version) ----------
__device__ __forceinline__ void grid_sync() {
    __syncthreads();
    if (threadIdx.x == 0) {
        const unsigned gen = g_bar_gen;
        const int b = blockIdx.x & 7;
        const unsigned cnt = 18u + (b < 4 ? 1u : 0u);   // 148 = 4*19 + 4*18
        __threadfence();
        if (atomicAdd(&g_bar_leaf[b], 1u) == cnt - 1u) {
            atomicExch(&g_bar_leaf[b], 0u);
            if (atomicAdd(&g_bar_root, 1u) == 7u) {
                atomicExch(&g_bar_root, 0u);
                __threadfence();
                g_bar_gen = gen + 1u;
            } else {
                while (g_bar_gen == gen) { __nanosleep(32); }
            }
        } else {
            while (g_bar_gen == gen) { __nanosleep(32); }
        }
        __threadfence();
    }
    __syncthreads();
}

// named barrier among compute warps only
__device__ __forceinline__ void barn() {
    asm volatile("bar.sync 1, %0;" :: "n"(CTHR) : "memory");
}

// ---------------- loader stream: real coalesced reads, self-throttled -------
__device__ __forceinline__ void stream_read(const float* __restrict__ p,
                                            unsigned nfloats, unsigned lw,
                                            int lane, float& dummy) {
    const float4* q = (const float4*)p;
    const unsigned nv = nfloats >> 2;
    for (unsigned base = lw * 256u; base < nv; base += LW_TOT * 256u) {
        float4 acc[8];
        #pragma unroll
        for (int t = 0; t < 8; t++) acc[t] = q[base + (unsigned)lane + 32u * t];
        #pragma unroll
        for (int t = 0; t < 8; t++)
            dummy += acc[t].x + acc[t].y + acc[t].z + acc[t].w;
    }
}

// ---------------- reductions -------------------------------------------------
__device__ __forceinline__ float block_sum_c(float v, float* red) {
    #pragma unroll
    for (int o = 16; o; o >>= 1) v += __shfl_xor_sync(0xffffffffu, v, o);
    int w = threadIdx.x >> 5;
    if ((threadIdx.x & 31) == 0) red[w] = v;
    barn();
    if (threadIdx.x < 32) {
        float t = (threadIdx.x < CWARP) ? red[threadIdx.x] : 0.f;
        #pragma unroll
        for (int o = 16; o; o >>= 1) t += __shfl_xor_sync(0xffffffffu, t, o);
        if (threadIdx.x == 0) red[0] = t;
    }
    barn();
    float r = red[0];
    barn();
    return r;
}

__device__ __forceinline__ float block_sum_all(float v, float* red) {
    #pragma unroll
    for (int o = 16; o; o >>= 1) v += __shfl_xor_sync(0xffffffffu, v, o);
    int w = threadIdx.x >> 5;
    if ((threadIdx.x & 31) == 0) red[w] = v;
    __syncthreads();
    if (threadIdx.x < 32) {
        float t = (threadIdx.x < NWALL) ? red[threadIdx.x] : 0.f;
        #pragma unroll
        for (int o = 16; o; o >>= 1) t += __shfl_xor_sync(0xffffffffu, t, o);
        if (threadIdx.x == 0) red[0] = t;
    }
    __syncthreads();
    float r = red[0];
    __syncthreads();
    return r;
}

// LN by compute warps only (stride CTHR, named barriers)
__device__ void block_ln_c(const float* __restrict__ src,
                           const float* __restrict__ w,
                           const float* __restrict__ b,
                           float* dst, float* red) {
    float s = 0.f;
    for (int j = threadIdx.x; j < E; j += CTHR) { float t = src[j]; dst[j] = t; s += t; }
    float mean = block_sum_c(s, red) * (1.f / E);
    float s2 = 0.f;
    for (int j = threadIdx.x; j < E; j += CTHR) { float c = dst[j] - mean; s2 += c * c; }
    float inv = rsqrtf(block_sum_c(s2, red) * (1.f / E) + 1e-5f);
    for (int j = threadIdx.x; j < E; j += CTHR)
        dst[j] = (dst[j] - mean) * inv * w[j] + b[j];
    barn();
}

// LN by all threads (init + head)
__device__ void block_ln_all(const float* __restrict__ src,
                             const float* __restrict__ w,
                             const float* __restrict__ b,
                             float* dst, float* red) {
    float s = 0.f;
    for (int j = threadIdx.x; j < E; j += NTHR) { float t = src[j]; dst[j] = t; s += t; }
    float mean = block_sum_all(s, red) * (1.f / E);
    float s2 = 0.f;
    for (int j = threadIdx.x; j < E; j += NTHR) { float c = dst[j] - mean; s2 += c * c; }
    float inv = rsqrtf(block_sum_all(s2, red) * (1.f / E) + 1e-5f);
    for (int j = threadIdx.x; j < E; j += NTHR)
        dst[j] = (dst[j] - mean) * inv * w[j] + b[j];
    __syncthreads();
}

// ---------------- GEMV pieces ------------------------------------------------
__device__ __forceinline__ float red32(float s) {
    #pragma unroll
    for (int o = 16; o; o >>= 1) s += __shfl_xor_sync(0xffffffffu, s, o);
    return s;
}

__device__ __forceinline__ void pf8(const float* __restrict__ Wrow, int lane,
                                    float4 (&a)[8]) {
    const float4* W = (const float4*)Wrow;
    #pragma unroll
    for (int t = 0; t < 8; t++) a[t] = W[lane + 32 * t];
}

__device__ __forceinline__ float dot8_pf(const float4 (&a)[8],
                                         const float* __restrict__ vec, int lane) {
    const float4* v = (const float4*)vec;
    float s = 0.f;
    #pragma unroll
    for (int t = 0; t < 8; t++) {
        float4 x = v[lane + 32 * t];
        s = fmaf(a[t].x, x.x, s); s = fmaf(a[t].y, x.y, s);
        s = fmaf(a[t].z, x.z, s); s = fmaf(a[t].w, x.w, s);
    }
    return red32(s);
}

__device__ __forceinline__ float warp_dot8(const float* __restrict__ Wrow,
                                           const float* __restrict__ vec, int lane) {
    float4 a[8];
    pf8(Wrow, lane, a);
    return dot8_pf(a, vec, lane);
}

__device__ __forceinline__ float dot32_pf(float4 (&a)[8],
                                          const float* __restrict__ Wrow,
                                          const float* __restrict__ vec, int lane) {
    const float4* W = (const float4*)Wrow;
    const float4* v = (const float4*)vec;
    float4 b[8];
    float s = 0.f;
    #pragma unroll
    for (int c = 0; c < 4; c++) {
        if (c < 3) {
            #pragma unroll
            for (int t = 0; t < 8; t++) b[t] = W[lane + 32 * t + 256 * (c + 1)];
        }
        #pragma unroll
        for (int t = 0; t < 8; t++) {
            float4 x = v[lane + 32 * t + 256 * c];
            s = fmaf(a[t].x, x.x, s); s = fmaf(a[t].y, x.y, s);
            s = fmaf(a[t].z, x.z, s); s = fmaf(a[t].w, x.w, s);
        }
        #pragma unroll
        for (int t = 0; t < 8; t++) a[t] = b[t];
    }
    return red32(s);
}

__device__ __forceinline__ float sigmoidf_(float x) {
    return 1.f / (1.f + expf(-x));
}

__device__ __forceinline__ const float* wrowA(const Params& p, int l, int row) {
    int m = row >> 10, i = row & (E - 1);
    const float* Wb = (m == 0) ? p.Wr : (m == 1) ? p.Wk : p.Wv;
    return Wb + (size_t)l * E * E + (size_t)i * E;
}

// ---------------- the whole network in one persistent kernel ----------------
__global__ void __launch_bounds__(NTHR, 1) rwkv_kernel(Params p) {
    __shared__ __align__(16) float sh[HID];   // 16KB, aliased per phase
    __shared__ float red[NWALL];

    const int tid  = threadIdx.x;
    const int wid  = tid >> 5;
    const int lane = tid & 31;
    const bool isload = (wid >= CWARP);
    const int gw   = blockIdx.x * CWARP + wid;                // compute warp id
    const unsigned lw = blockIdx.x * LWARP + (wid - CWARP);   // loader warp id
    const int ghw  = blockIdx.x * NWALL + wid;                // head warp id

    float* outv  = p.out;
    float* o_xx  = p.out + VOCAB;
    float* o_aa  = o_xx  + LAY * E;
    float* o_bb  = o_aa  + LAY * E;
    float* o_pp  = o_bb  + LAY * E;
    float* o_xxf = o_pp  + LAY * E;
    float* o_da  = o_xxf + LAY * E;
    float* o_db  = o_da  + LAY * E;

    float4 a[8];
    float dummy = 0.f;

    // ---- init: x0 = LN(emb[ctx], ln0) (all threads) ----
    {
        int tok = p.ctx[0];
        block_ln_all(p.emb_w + (size_t)tok * E, p.ln0_w, p.ln0_b, sh, red);
        if (blockIdx.x == 0)
            for (int j = tid; j < E; j += NTHR) g_x[j] = sh[j];
    }
    if (!isload) {
        pf8(wrowA(p, 0, gw), lane, a);
    } else {
        stream_read(p.Wr, E * E, lw, lane, dummy);
        stream_read(p.Wk, E * E, lw, lane, dummy);
        stream_read(p.Wv, E * E, lw, lane, dummy);
        stream_read(p.ln1_w, E, lw, lane, dummy);
        stream_read(p.ln1_b, E, lw, lane, dummy);
        stream_read(p.xx_att, E, lw, lane, dummy);
        stream_read(p.mk, E, lw, lane, dummy);
        stream_read(p.mv, E, lw, lane, dummy);
        stream_read(p.mr, E, lw, lane, dummy);
    }
    grid_sync();

    for (int l = 0; l < LAY; l++) {
        const size_t lE  = (size_t)l * E;
        const size_t lEE = (size_t)l * E * E;
        const size_t lHE = (size_t)l * HID * E;
        const size_t lEH = (size_t)l * E * HID;

        // ================= Phase A =========================================
        if (isload) {
            stream_read(p.Wo + lEE, E * E, lw, lane, dummy);
            stream_read(p.aa_att + lE, E, lw, lane, dummy);
            stream_read(p.bb_att + lE, E, lw, lane, dummy);
            stream_read(p.pp_att + lE, E, lw, lane, dummy);
            stream_read(p.tf + lE, E, lw, lane, dummy);
            stream_read(p.td + lE, E, lw, lane, dummy);
            stream_read(p.Fk + lHE, 3 * E * E, lw, lane, dummy);   // 3/4 of Fk
        } else {
            float* xn = sh; float* xk = sh + E; float* xv = sh + 2 * E; float* xr = sh + 3 * E;
            block_ln_c(g_x, p.ln1_w + lE, p.ln1_b + lE, xn, red);
            for (int j = tid; j < E; j += CTHR) {
                float xnj = xn[j], sx = p.xx_att[lE + j];
                float ak = p.mk[lE + j], bv = p.mv[lE + j], cr = p.mr[lE + j];
                xk[j] = xnj * ak + sx * (1.f - ak);
                xv[j] = xnj * bv + sx * (1.f - bv);
                xr[j] = xnj * cr + sx * (1.f - cr);
                if (blockIdx.x == 0) o_xx[lE + j] = xnj;
            }
            barn();
            {
                int m = gw >> 10, i = gw & (E - 1);
                const float* vec = (m == 0) ? xr : (m == 1) ? xk : xv;
                float s = dot8_pf(a, vec, lane);
                if (lane == 0) ((m == 0) ? g_r : (m == 1) ? g_k : g_v)[i] = s;
            }
            if (gw < 3 * E - GW_C) {                 // round 2: rows 1776..3071
                int row = gw + GW_C;
                int m = row >> 10, i = row & (E - 1);
                const float* vec = (m == 0) ? xr : (m == 1) ? xk : xv;
                float s = warp_dot8(wrowA(p, l, row), vec, lane);
                if (lane == 0) ((m == 0) ? g_r : (m == 1) ? g_k : g_v)[i] = s;
            }
            if (gw < E) pf8(p.Wo + lEE + (size_t)gw * E, lane, a);
        }
        grid_sync();

        // ================= Phase B =========================================
        if (isload) {
            stream_read(p.Fk + lHE + 3 * E * E, E * E, lw, lane, dummy); // rest of Fk
            stream_read(p.Fr + lEE, E * E, lw, lane, dummy);
            stream_read(p.ln2_w + lE, E, lw, lane, dummy);
            stream_read(p.ln2_b + lE, E, lw, lane, dummy);
            stream_read(p.xx_ffn + lE, E, lw, lane, dummy);
            stream_read(p.fmk + lE, E, lw, lane, dummy);
            stream_read(p.fmr + lE, E, lw, lane, dummy);
        } else {
            float* oin = sh;
            for (int j = tid; j < E; j += CTHR) {
                float kj = g_k[j], vj = g_v[j], rp = g_r[j];
                float aa = p.aa_att[lE + j], bb = p.bb_att[lE + j], pp = p.pp_att[lE + j];
                float tf = p.tf[lE + j],     td = p.td[lE + j];
                float ww = tf + kj;
                float q  = fmaxf(pp, ww);
                float e1 = expf(pp - q), e2 = expf(ww - q);
                float av = e1 * aa + e2 * vj;
                float bv = e1 * bb + e2;
                float rr = sigmoidf_(rp);
                oin[j] = rr * av / bv;
                if (blockIdx.x == 0) {
                    float ww2 = pp + td;
                    float q2  = fmaxf(ww2, kj);
                    float f1  = expf(ww2 - q2), f2 = expf(kj - q2);
                    o_aa[lE + j] = f1 * aa + f2 * vj;
                    o_bb[lE + j] = f1 * bb + f2;
                    o_pp[lE + j] = q2;
                    o_da[lE + j] = rp;
                    o_db[lE + j] = rr;
                }
            }
            barn();
            if (gw < E) {
                float s = dot8_pf(a, oin, lane);
                if (lane == 0) g_x[gw] += s;
            }
            pf8(p.Fk + lHE + (size_t)gw * E, lane, a);
        }
        grid_sync();

        // ================= Phase C =========================================
        if (isload) {
            stream_read(p.Fv + lEH, E * HID, lw, lane, dummy);
        } else {
            float* xn2 = sh; float* fxk = sh + E; float* fxr = sh + 2 * E;
            block_ln_c(g_x, p.ln2_w + lE, p.ln2_b + lE, xn2, red);
            for (int j = tid; j < E; j += CTHR) {
                float v = xn2[j], sxf = p.xx_ffn[lE + j];
                float ak = p.fmk[lE + j], br = p.fmr[lE + j];
                fxk[j] = v * ak + sxf * (1.f - ak);
                fxr[j] = v * br + sxf * (1.f - br);
                if (blockIdx.x == 0) o_xxf[lE + j] = v;
            }
            barn();
            {
                float s = dot8_pf(a, fxk, lane);
                s = fmaxf(s, 0.f);
                if (lane == 0) g_kf[gw] = s * s;
            }
            {
                int row2 = gw + GW_C;                       // 1776..3551, all Fk
                float s = warp_dot8(p.Fk + lHE + (size_t)row2 * E, fxk, lane);
                s = fmaxf(s, 0.f);
                if (lane == 0) g_kf[row2] = s * s;
            }
            if (gw < HID + E - 2 * GW_C) {                  // round 3: gw < 1568
                int row3 = gw + 2 * GW_C;
                if (row3 < HID) {
                    float s = warp_dot8(p.Fk + lHE + (size_t)row3 * E, fxk, lane);
                    s = fmaxf(s, 0.f);
                    if (lane == 0) g_kf[row3] = s * s;
                } else {
                    int i = row3 - HID;
                    float s = warp_dot8(p.Fr + lEE + (size_t)i * E, fxr, lane);
                    if (lane == 0) g_rf[i] = sigmoidf_(s);
                }
            }
            if (gw < E) pf8(p.Fv + lEH + (size_t)gw * HID, lane, a);
        }
        grid_sync();

        // ================= Phase D =========================================
        if (isload) {
            if (l + 1 < LAY) {
                const size_t nEE = lEE + E * E;
                stream_read(p.Wr + nEE, E * E, lw, lane, dummy);
                stream_read(p.Wk + nEE, E * E, lw, lane, dummy);
                stream_read(p.Wv + nEE, E * E, lw, lane, dummy);
                stream_read(p.ln1_w + lE + E, E, lw, lane, dummy);
                stream_read(p.ln1_b + lE + E, E, lw, lane, dummy);
                stream_read(p.xx_att + lE + E, E, lw, lane, dummy);
                stream_read(p.mk + lE + E, E, lw, lane, dummy);
                stream_read(p.mv + lE + E, E, lw, lane, dummy);
                stream_read(p.mr + lE + E, E, lw, lane, dummy);
            } else {
                stream_read(p.head_w, 8 * 1024 * 1024, lw, lane, dummy);  // 32MB
                pf8(p.head_w + (size_t)ghw * E, lane, a);
            }
        } else {
            {
                const float4* kf4 = (const float4*)g_kf;
                float4* sh4 = (float4*)sh;
                for (int j = tid; j < HID / 4; j += CTHR) sh4[j] = kf4[j];
            }
            barn();
            if (gw < E) {
                float s = dot32_pf(a, p.Fv + lEH + (size_t)gw * HID, sh, lane);
                if (lane == 0) g_x[gw] += g_rf[gw] * s;
            }
            if (l + 1 < LAY) pf8(wrowA(p, l + 1, gw), lane, a);
            else             pf8(p.head_w + (size_t)ghw * E, lane, a);
        }
        grid_sync();
    }

    // ================= head: LN + [V,E] GEMV (all 16 warps) ================
    block_ln_all(g_x, p.lno_w, p.lno_b, sh, red);
    {
        float4 b[8];
        int row = ghw;
        if (row + GW_H < VOCAB) pf8(p.head_w + (size_t)(row + GW_H) * E, lane, b);
        while (true) {
            float s = dot8_pf(a, sh, lane);
            if (lane == 0) outv[row] = s;
            int rn = row + GW_H;
            if (rn >= VOCAB) break;
            int rp = row + 2 * GW_H;
            if (rp < VOCAB) pf8(p.head_w + (size_t)rp * E, lane, a);
            s = dot8_pf(b, sh, lane);
            if (lane == 0) outv[rn] = s;
            row = rp;
            if (row >= VOCAB) break;
            int rq = rn + 2 * GW_H;
            if (rq < VOCAB) pf8(p.head_w + (size_t)rq * E, lane, b);
        }
    }
    if (dummy == 1.2345e-33f) g_sink = dummy;   // keep loader reads alive
}

extern "C" void kernel_launch(void* const* d_in, const int* in_sizes, int n_in,
                              void* d_out, int out_size) {
    Params p;
    p.ctx    = (const int*)  d_in[0];
    p.xx_att = (const float*)d_in[1];
    p.aa_att = (const float*)d_in[2];
    p.bb_att = (const float*)d_in[3];
    p.pp_att = (const float*)d_in[4];
    p.xx_ffn = (const float*)d_in[5];
    p.emb_w  = (const float*)d_in[6];
    p.head_w = (const float*)d_in[7];
    p.ln0_w  = (const float*)d_in[8];
    p.ln0_b  = (const float*)d_in[9];
    p.ln1_w  = (const float*)d_in[10];
    p.ln1_b  = (const float*)d_in[11];
    p.ln2_w  = (const float*)d_in[12];
    p.ln2_b  = (const float*)d_in[13];
    p.lno_w  = (const float*)d_in[14];
    p.lno_b  = (const float*)d_in[15];
    p.mk     = (const float*)d_in[16];
    p.mv     = (const float*)d_in[17];
    p.mr     = (const float*)d_in[18];
    p.tf     = (const float*)d_in[19];
    p.td     = (const float*)d_in[20];
    p.Wr     = (const float*)d_in[21];
    p.Wk     = (const float*)d_in[22];
    p.Wv     = (const float*)d_in[23];
    p.Wo     = (const float*)d_in[24];
    p.fmk    = (const float*)d_in[25];
    p.fmr    = (const float*)d_in[26];
    p.Fr     = (const float*)d_in[27];
    p.Fk     = (const float*)d_in[28];
    p.Fv     = (const float*)d_in[29];
    p.out    = (float*)d_out;

    rwkv_kernel<<<NBLK, NTHR>>>(p);
}

// round 7
// speedup vs baseline: 1.1011x; 1.0956x over previous
#include <cuda_runtime.h>

#define E     1024
#define LAY   24
#define HID   4096
#define VOCAB 50277
#define NBLK  148
#define NTHR  512
#define NWARP (NTHR / 32)
#define GWARPS (NBLK * NWARP)   // 2368

// ---------------- scratch (device globals: no allocations allowed) ----------
__device__ __align__(16) float g_x[E];
__device__ __align__(16) float g_r[E];
__device__ __align__(16) float g_k[E];
__device__ __align__(16) float g_v[E];
__device__ __align__(16) float g_rf[E];
__device__ __align__(16) float g_kf[HID];
__device__ unsigned g_bar_leaf[8] = {0,0,0,0,0,0,0,0};
__device__ unsigned g_bar_root = 0;
__device__ volatile unsigned g_bar_gen = 0;

struct Params {
    const int*   ctx;
    const float *xx_att, *aa_att, *bb_att, *pp_att, *xx_ffn;
    const float *emb_w, *head_w;
    const float *ln0_w, *ln0_b, *ln1_w, *ln1_b, *ln2_w, *ln2_b, *lno_w, *lno_b;
    const float *mk, *mv, *mr, *tf, *td;
    const float *Wr, *Wk, *Wv, *Wo;
    const float *fmk, *fmr, *Fr, *Fk, *Fv;
    float* out;
};

// ------------- two-level software grid barrier (R3-proven version) ----------
__device__ __forceinline__ void grid_sync() {
    __syncthreads();
    if (threadIdx.x == 0) {
        const unsigned gen = g_bar_gen;
        const int b = blockIdx.x & 7;
        const unsigned cnt = 18u + (b < 4 ? 1u : 0u);   // 148 = 4*19 + 4*18
        __threadfence();
        if (atomicAdd(&g_bar_leaf[b], 1u) == cnt - 1u) {
            atomicExch(&g_bar_leaf[b], 0u);
            if (atomicAdd(&g_bar_root, 1u) == 7u) {
                atomicExch(&g_bar_root, 0u);
                __threadfence();
                g_bar_gen = gen + 1u;
            } else {
                while (g_bar_gen == gen) { __nanosleep(32); }
            }
        } else {
            while (g_bar_gen == gen) { __nanosleep(32); }
        }
        __threadfence();
    }
    __syncthreads();
}

// ---------------- block reduction (sum, broadcast) ---------------------------
__device__ __forceinline__ float block_sum(float v, float* red) {
    #pragma unroll
    for (int o = 16; o; o >>= 1) v += __shfl_xor_sync(0xffffffffu, v, o);
    int w = threadIdx.x >> 5;
    if ((threadIdx.x & 31) == 0) red[w] = v;
    __syncthreads();
    if (threadIdx.x < 32) {
        float t = (threadIdx.x < NWARP) ? red[threadIdx.x] : 0.f;
        #pragma unroll
        for (int o = 16; o; o >>= 1) t += __shfl_xor_sync(0xffffffffu, t, o);
        if (threadIdx.x == 0) red[0] = t;
    }
    __syncthreads();
    float r = red[0];
    __syncthreads();
    return r;
}

// two-pass LayerNorm: src (global) -> dst (shared), per-block redundant
__device__ void block_ln(const float* __restrict__ src,
                         const float* __restrict__ w,
                         const float* __restrict__ b,
                         float* dst, float* red) {
    float s = 0.f;
    for (int j = threadIdx.x; j < E; j += NTHR) { float t = src[j]; dst[j] = t; s += t; }
    float mean = block_sum(s, red) * (1.f / E);
    float s2 = 0.f;
    for (int j = threadIdx.x; j < E; j += NTHR) { float c = dst[j] - mean; s2 += c * c; }
    float inv = rsqrtf(block_sum(s2, red) * (1.f / E) + 1e-5f);
    for (int j = threadIdx.x; j < E; j += NTHR)
        dst[j] = (dst[j] - mean) * inv * w[j] + b[j];
    __syncthreads();
}

// ---------------- GEMV pieces ------------------------------------------------
__device__ __forceinline__ float red32(float s) {
    #pragma unroll
    for (int o = 16; o; o >>= 1) s += __shfl_xor_sync(0xffffffffu, s, o);
    return s;
}

__device__ __forceinline__ void pf8(const float* __restrict__ Wrow, int lane,
                                    float4 (&a)[8]) {
    const float4* W = (const float4*)Wrow;
    #pragma unroll
    for (int t = 0; t < 8; t++) a[t] = W[lane + 32 * t];
}

// partial dot (no reduce) — for multi-chunk accumulation
__device__ __forceinline__ float dot8_acc(const float4 (&a)[8],
                                          const float* __restrict__ vec,
                                          int lane, float s) {
    const float4* v = (const float4*)vec;
    #pragma unroll
    for (int t = 0; t < 8; t++) {
        float4 x = v[lane + 32 * t];
        s = fmaf(a[t].x, x.x, s); s = fmaf(a[t].y, x.y, s);
        s = fmaf(a[t].z, x.z, s); s = fmaf(a[t].w, x.w, s);
    }
    return s;
}

__device__ __forceinline__ float dot8_pf(const float4 (&a)[8],
                                         const float* __restrict__ vec, int lane) {
    return red32(dot8_acc(a, vec, lane, 0.f));
}

__device__ __forceinline__ float sigmoidf_(float x) {
    return 1.f / (1.f + expf(-x));
}

__device__ __forceinline__ const float* wrowA(const Params& p, int l, int row) {
    int m = row >> 10, i = row & (E - 1);
    const float* Wb = (m == 0) ? p.Wr : (m == 1) ? p.Wk : p.Wv;
    return Wb + (size_t)l * E * E + (size_t)i * E;
}

// ---------------- the whole network in one persistent kernel ----------------
__global__ void __launch_bounds__(NTHR, 1) rwkv_kernel(Params p) {
    __shared__ __align__(16) float sh[HID];   // 16KB, aliased per phase
    __shared__ float red[NWARP];

    const int tid  = threadIdx.x;
    const int gw   = blockIdx.x * NWARP + (tid >> 5);
    const int lane = tid & 31;

    float* outv  = p.out;                 // logits [V]
    float* o_xx  = p.out + VOCAB;         // xx_att_r [L,E]
    float* o_aa  = o_xx  + LAY * E;
    float* o_bb  = o_aa  + LAY * E;
    float* o_pp  = o_bb  + LAY * E;
    float* o_xxf = o_pp  + LAY * E;
    float* o_da  = o_xxf + LAY * E;       // r_pre
    float* o_db  = o_da  + LAY * E;       // sigmoid(r_pre)

    float4 a[8];                          // persistent cross-barrier buffer

    // ---- init: x0 = LN(emb[ctx], ln0) ----
    {
        int tok = p.ctx[0];
        block_ln(p.emb_w + (size_t)tok * E, p.ln0_w, p.ln0_b, sh, red);
        if (blockIdx.x == 0)
            for (int j = tid; j < E; j += NTHR) g_x[j] = sh[j];
    }
    pf8(wrowA(p, 0, gw), lane, a);
    grid_sync();

    for (int l = 0; l < LAY; l++) {
        const size_t lE  = (size_t)l * E;
        const size_t lEE = (size_t)l * E * E;
        const size_t lHE = (size_t)l * HID * E;
        const size_t lEH = (size_t)l * E * HID;

        // ================= Phase A: LN1 + mixes + r/k/v GEMVs ==============
        {
            // early demand-issue for round 2 (rows 2368..3071 — all Wv)
            const bool hasA2 = (gw < 3 * E - GWARPS);   // gw < 704
            float4 b2[8];
            if (hasA2)
                pf8(p.Wv + lEE + (size_t)(gw + GWARPS - 2048) * E, lane, b2);

            float* xn = sh; float* xk = sh + E; float* xv = sh + 2 * E; float* xr = sh + 3 * E;
            block_ln(g_x, p.ln1_w + lE, p.ln1_b + lE, xn, red);
            for (int j = tid; j < E; j += NTHR) {
                float xnj = xn[j], sx = p.xx_att[lE + j];
                float ak = p.mk[lE + j], bv = p.mv[lE + j], cr = p.mr[lE + j];
                xk[j] = xnj * ak + sx * (1.f - ak);
                xv[j] = xnj * bv + sx * (1.f - bv);
                xr[j] = xnj * cr + sx * (1.f - cr);
                if (blockIdx.x == 0) o_xx[lE + j] = xnj;
            }
            __syncthreads();
            {
                int m = gw >> 10, i = gw & (E - 1);
                const float* vec = (m == 0) ? xr : (m == 1) ? xk : xv;
                float s = dot8_pf(a, vec, lane);
                if (lane == 0) ((m == 0) ? g_r : (m == 1) ? g_k : g_v)[i] = s;
            }
            if (hasA2) {
                float s = dot8_pf(b2, xv, lane);
                if (lane == 0) g_v[gw + GWARPS - 2048] = s;
            }
            if (gw < E) pf8(p.Wo + lEE + (size_t)gw * E, lane, a);
        }
        grid_sync();

        // ================= Phase B: WKV elementwise + Wo GEMV ==============
        {
            float* oin = sh;
            for (int j = tid; j < E; j += NTHR) {
                float kj = g_k[j], vj = g_v[j], rp = g_r[j];
                float aa = p.aa_att[lE + j], bb = p.bb_att[lE + j], pp = p.pp_att[lE + j];
                float tf = p.tf[lE + j],     td = p.td[lE + j];
                float ww = tf + kj;
                float q  = fmaxf(pp, ww);
                float e1 = expf(pp - q), e2 = expf(ww - q);
                float av = e1 * aa + e2 * vj;
                float bv = e1 * bb + e2;
                float rr = sigmoidf_(rp);
                oin[j] = rr * av / bv;
                if (blockIdx.x == 0) {
                    float ww2 = pp + td;
                    float q2  = fmaxf(ww2, kj);
                    float f1  = expf(ww2 - q2), f2 = expf(kj - q2);
                    o_aa[lE + j] = f1 * aa + f2 * vj;
                    o_bb[lE + j] = f1 * bb + f2;
                    o_pp[lE + j] = q2;
                    o_da[lE + j] = rp;
                    o_db[lE + j] = rr;
                }
            }
            __syncthreads();
            if (gw < E) {
                float s = dot8_pf(a, oin, lane);
                if (lane == 0) g_x[gw] += s;
            }
            pf8(p.Fk + lHE + (size_t)gw * E, lane, a);   // phase-C row 1
        }
        grid_sync();

        // ================= Phase C: LN2 + mixes + Fk/Fr GEMVs ==============
        {
            // early demand-issue for round 2 (Fk row if < HID, else Fr row)
            const int row2 = gw + GWARPS;                // 2368..4735
            float4 b2[8];
            pf8((row2 < HID) ? p.Fk + lHE + (size_t)row2 * E
                             : p.Fr + lEE + (size_t)(row2 - HID) * E, lane, b2);

            float* xn2 = sh; float* fxk = sh + E; float* fxr = sh + 2 * E;
            block_ln(g_x, p.ln2_w + lE, p.ln2_b + lE, xn2, red);
            for (int j = tid; j < E; j += NTHR) {
                float v = xn2[j], sxf = p.xx_ffn[lE + j];
                float ak = p.fmk[lE + j], br = p.fmr[lE + j];
                fxk[j] = v * ak + sxf * (1.f - ak);
                fxr[j] = v * br + sxf * (1.f - br);
                if (blockIdx.x == 0) o_xxf[lE + j] = v;
            }
            __syncthreads();
            {
                float s = dot8_pf(a, fxk, lane);
                s = fmaxf(s, 0.f);
                if (lane == 0) g_kf[gw] = s * s;
            }
            // round 3 exists only for gw < 384 (rows 4736..5119 — all Fr)
            const bool has3 = (gw < HID + E - 2 * GWARPS);
            if (has3)
                pf8(p.Fr + lEE + (size_t)(gw + 2 * GWARPS - HID) * E, lane, a);
            {
                float s = dot8_pf(b2, (row2 < HID) ? fxk : fxr, lane);
                if (lane == 0) {
                    if (row2 < HID) { s = fmaxf(s, 0.f); g_kf[row2] = s * s; }
                    else            g_rf[row2 - HID] = sigmoidf_(s);
                }
            }
            if (has3) {
                float s = dot8_pf(a, fxr, lane);
                if (lane == 0) g_rf[gw + 2 * GWARPS - HID] = sigmoidf_(s);
            }
            if (gw < E) pf8(p.Fv + lEH + (size_t)gw * HID, lane, a);  // D chunk0
        }
        grid_sync();

        // ================= Phase D: Fv GEMV + residual add =================
        {
            const float* Wrow = p.Fv + lEH + (size_t)gw * HID;
            float4 b2[8];
            if (gw < E) pf8(Wrow + 1024, lane, b2);      // chunk1 early issue
            {
                const float4* kf4 = (const float4*)g_kf;
                float4* sh4 = (float4*)sh;
                for (int j = tid; j < HID / 4; j += NTHR) sh4[j] = kf4[j];
            }
            __syncthreads();
            if (gw < E) {
                float s = dot8_acc(a, sh, lane, 0.f);          // chunk0
                pf8(Wrow + 2048, lane, a);                     // chunk2
                s = dot8_acc(b2, sh + 1024, lane, s);          // chunk1
                pf8(Wrow + 3072, lane, b2);                    // chunk3
                s = dot8_acc(a, sh + 2048, lane, s);           // chunk2
                s = dot8_acc(b2, sh + 3072, lane, s);          // chunk3
                s = red32(s);
                if (lane == 0) g_x[gw] += g_rf[gw] * s;
            }
            if (l + 1 < LAY) pf8(wrowA(p, l + 1, gw), lane, a);
            else             pf8(p.head_w + (size_t)gw * E, lane, a);
        }
        grid_sync();
    }

    // ================= head: LN + [V,E] GEMV (ping-pong) ===================
    block_ln(g_x, p.lno_w, p.lno_b, sh, red);
    {
        float4 b[8];
        int row = gw;
        if (row + GWARPS < VOCAB) pf8(p.head_w + (size_t)(row + GWARPS) * E, lane, b);
        while (true) {
            float s = dot8_pf(a, sh, lane);
            if (lane == 0) outv[row] = s;
            int rn = row + GWARPS;
            if (rn >= VOCAB) break;
            int rp = row + 2 * GWARPS;
            if (rp < VOCAB) pf8(p.head_w + (size_t)rp * E, lane, a);
            s = dot8_pf(b, sh, lane);
            if (lane == 0) outv[rn] = s;
            row = rp;
            if (row >= VOCAB) break;
            int rq = rn + 2 * GWARPS;
            if (rq < VOCAB) pf8(p.head_w + (size_t)rq * E, lane, b);
        }
    }
}

extern "C" void kernel_launch(void* const* d_in, const int* in_sizes, int n_in,
                              void* d_out, int out_size) {
    Params p;
    p.ctx    = (const int*)  d_in[0];
    p.xx_att = (const float*)d_in[1];
    p.aa_att = (const float*)d_in[2];
    p.bb_att = (const float*)d_in[3];
    p.pp_att = (const float*)d_in[4];
    p.xx_ffn = (const float*)d_in[5];
    p.emb_w  = (const float*)d_in[6];
    p.head_w = (const float*)d_in[7];
    p.ln0_w  = (const float*)d_in[8];
    p.ln0_b  = (const float*)d_in[9];
    p.ln1_w  = (const float*)d_in[10];
    p.ln1_b  = (const float*)d_in[11];
    p.ln2_w  = (const float*)d_in[12];
    p.ln2_b  = (const float*)d_in[13];
    p.lno_w  = (const float*)d_in[14];
    p.lno_b  = (const float*)d_in[15];
    p.mk     = (const float*)d_in[16];
    p.mv     = (const float*)d_in[17];
    p.mr     = (const float*)d_in[18];
    p.tf     = (const float*)d_in[19];
    p.td     = (const float*)d_in[20];
    p.Wr     = (const float*)d_in[21];
    p.Wk     = (const float*)d_in[22];
    p.Wv     = (const float*)d_in[23];
    p.Wo     = (const float*)d_in[24];
    p.fmk    = (const float*)d_in[25];
    p.fmr    = (const float*)d_in[26];
    p.Fr     = (const float*)d_in[27];
    p.Fk     = (const float*)d_in[28];
    p.Fv     = (const float*)d_in[29];
    p.out    = (float*)d_out;

    rwkv_kernel<<<NBLK, NTHR>>>(p);
}

// round 8
// speedup vs baseline: 1.2310x; 1.1179x over previous
#include <cuda_runtime.h>

#define E     1024
#define LAY   24
#define HID   4096
#define VOCAB 50277
#define NBLK  148
#define NTHR  512
#define NWARP (NTHR / 32)
#define GWARPS (NBLK * NWARP)   // 2368

// ---------------- scratch (device globals: no allocations allowed) ----------
__device__ __align__(16) float g_x[E];
__device__ __align__(16) float g_r[E];
__device__ __align__(16) float g_k[E];
__device__ __align__(16) float g_v[E];
__device__ __align__(16) float g_rf[E];
__device__ __align__(16) float g_kf[HID];
__device__ unsigned g_bar_leaf[8] = {0,0,0,0,0,0,0,0};
__device__ unsigned g_bar_root = 0;
__device__ volatile unsigned g_bar_gen = 0;

struct Params {
    const int*   ctx;
    const float *xx_att, *aa_att, *bb_att, *pp_att, *xx_ffn;
    const float *emb_w, *head_w;
    const float *ln0_w, *ln0_b, *ln1_w, *ln1_b, *ln2_w, *ln2_b, *lno_w, *lno_b;
    const float *mk, *mv, *mr, *tf, *td;
    const float *Wr, *Wk, *Wv, *Wo;
    const float *fmk, *fmr, *Fr, *Fk, *Fv;
    float* out;
};

// ------------- two-level software grid barrier (R3-proven version) ----------
__device__ __forceinline__ void grid_sync() {
    __syncthreads();
    if (threadIdx.x == 0) {
        const unsigned gen = g_bar_gen;
        const int b = blockIdx.x & 7;
        const unsigned cnt = 18u + (b < 4 ? 1u : 0u);   // 148 = 4*19 + 4*18
        __threadfence();
        if (atomicAdd(&g_bar_leaf[b], 1u) == cnt - 1u) {
            atomicExch(&g_bar_leaf[b], 0u);
            if (atomicAdd(&g_bar_root, 1u) == 7u) {
                atomicExch(&g_bar_root, 0u);
                __threadfence();
                g_bar_gen = gen + 1u;
            } else {
                while (g_bar_gen == gen) { __nanosleep(32); }
            }
        } else {
            while (g_bar_gen == gen) { __nanosleep(32); }
        }
        __threadfence();
    }
    __syncthreads();
}

// ---------------- block reduction (sum, broadcast) ---------------------------
__device__ __forceinline__ float block_sum(float v, float* red) {
    #pragma unroll
    for (int o = 16; o; o >>= 1) v += __shfl_xor_sync(0xffffffffu, v, o);
    int w = threadIdx.x >> 5;
    if ((threadIdx.x & 31) == 0) red[w] = v;
    __syncthreads();
    if (threadIdx.x < 32) {
        float t = (threadIdx.x < NWARP) ? red[threadIdx.x] : 0.f;
        #pragma unroll
        for (int o = 16; o; o >>= 1) t += __shfl_xor_sync(0xffffffffu, t, o);
        if (threadIdx.x == 0) red[0] = t;
    }
    __syncthreads();
    float r = red[0];
    __syncthreads();
    return r;
}

// two-pass LayerNorm: src (global) -> dst (shared), per-block redundant
__device__ void block_ln(const float* __restrict__ src,
                         const float* __restrict__ w,
                         const float* __restrict__ b,
                         float* dst, float* red) {
    float s = 0.f;
    for (int j = threadIdx.x; j < E; j += NTHR) { float t = src[j]; dst[j] = t; s += t; }
    float mean = block_sum(s, red) * (1.f / E);
    float s2 = 0.f;
    for (int j = threadIdx.x; j < E; j += NTHR) { float c = dst[j] - mean; s2 += c * c; }
    float inv = rsqrtf(block_sum(s2, red) * (1.f / E) + 1e-5f);
    for (int j = threadIdx.x; j < E; j += NTHR)
        dst[j] = (dst[j] - mean) * inv * w[j] + b[j];
    __syncthreads();
}

// ---------------- GEMV pieces ------------------------------------------------
__device__ __forceinline__ float red32(float s) {
    #pragma unroll
    for (int o = 16; o; o >>= 1) s += __shfl_xor_sync(0xffffffffu, s, o);
    return s;
}

__device__ __forceinline__ void pf8(const float* __restrict__ Wrow, int lane,
                                    float4 (&a)[8]) {
    const float4* W = (const float4*)Wrow;
    #pragma unroll
    for (int t = 0; t < 8; t++) a[t] = W[lane + 32 * t];
}

// partial dot (no reduce) — for multi-chunk accumulation
__device__ __forceinline__ float dot8_acc(const float4 (&a)[8],
                                          const float* __restrict__ vec,
                                          int lane, float s) {
    const float4* v = (const float4*)vec;
    #pragma unroll
    for (int t = 0; t < 8; t++) {
        float4 x = v[lane + 32 * t];
        s = fmaf(a[t].x, x.x, s); s = fmaf(a[t].y, x.y, s);
        s = fmaf(a[t].z, x.z, s); s = fmaf(a[t].w, x.w, s);
    }
    return s;
}

__device__ __forceinline__ float dot8_pf(const float4 (&a)[8],
                                         const float* __restrict__ vec, int lane) {
    return red32(dot8_acc(a, vec, lane, 0.f));
}

__device__ __forceinline__ float sigmoidf_(float x) {
    return 1.f / (1.f + expf(-x));
}

__device__ __forceinline__ const float* wrowA(const Params& p, int l, int row) {
    int m = row >> 10, i = row & (E - 1);
    const float* Wb = (m == 0) ? p.Wr : (m == 1) ? p.Wk : p.Wv;
    return Wb + (size_t)l * E * E + (size_t)i * E;
}

// ---------------- the whole network in one persistent kernel ----------------
__global__ void __launch_bounds__(NTHR, 1) rwkv_kernel(Params p) {
    __shared__ __align__(16) float sh[HID];   // 16KB, aliased per phase
    __shared__ float red[NWARP];

    const int tid  = threadIdx.x;
    const int gw   = blockIdx.x * NWARP + (tid >> 5);
    const int lane = tid & 31;

    float* outv  = p.out;                 // logits [V]
    float* o_xx  = p.out + VOCAB;         // xx_att_r [L,E]
    float* o_aa  = o_xx  + LAY * E;
    float* o_bb  = o_aa  + LAY * E;
    float* o_pp  = o_bb  + LAY * E;
    float* o_xxf = o_pp  + LAY * E;
    float* o_da  = o_xxf + LAY * E;       // r_pre
    float* o_db  = o_da  + LAY * E;       // sigmoid(r_pre)

    float4 a[8];                          // persistent cross-barrier buffer

    // ---- init: x0 = LN(emb[ctx], ln0) ----
    {
        int tok = p.ctx[0];
        block_ln(p.emb_w + (size_t)tok * E, p.ln0_w, p.ln0_b, sh, red);
        if (blockIdx.x == 0)
            for (int j = tid; j < E; j += NTHR) g_x[j] = sh[j];
    }
    pf8(wrowA(p, 0, gw), lane, a);
    grid_sync();

    for (int l = 0; l < LAY; l++) {
        const size_t lE  = (size_t)l * E;
        const size_t lEE = (size_t)l * E * E;
        const size_t lHE = (size_t)l * HID * E;
        const size_t lEH = (size_t)l * E * HID;

        // ================= Phase A: LN1 + mixes + r/k/v GEMVs ==============
        {
            // early demand-issue for round 2 (rows 2368..3071 — all Wv)
            const bool hasA2 = (gw < 3 * E - GWARPS);   // gw < 704
            float4 b2[8];
            if (hasA2)
                pf8(p.Wv + lEE + (size_t)(gw + GWARPS - 2048) * E, lane, b2);

            float* xn = sh; float* xk = sh + E; float* xv = sh + 2 * E; float* xr = sh + 3 * E;
            block_ln(g_x, p.ln1_w + lE, p.ln1_b + lE, xn, red);
            for (int j = tid; j < E; j += NTHR) {
                float xnj = xn[j], sx = p.xx_att[lE + j];
                float ak = p.mk[lE + j], bv = p.mv[lE + j], cr = p.mr[lE + j];
                xk[j] = xnj * ak + sx * (1.f - ak);
                xv[j] = xnj * bv + sx * (1.f - bv);
                xr[j] = xnj * cr + sx * (1.f - cr);
                if (blockIdx.x == 0) o_xx[lE + j] = xnj;
            }
            __syncthreads();
            {
                int m = gw >> 10, i = gw & (E - 1);
                const float* vec = (m == 0) ? xr : (m == 1) ? xk : xv;
                float s = dot8_pf(a, vec, lane);
                if (lane == 0) ((m == 0) ? g_r : (m == 1) ? g_k : g_v)[i] = s;
            }
            if (hasA2) {
                float s = dot8_pf(b2, xv, lane);
                if (lane == 0) g_v[gw + GWARPS - 2048] = s;
            }
            if (gw < E) pf8(p.Wo + lEE + (size_t)gw * E, lane, a);
        }
        grid_sync();

        // ================= Phase B: WKV elementwise + Wo GEMV ==============
        {
            float* oin = sh;
            for (int j = tid; j < E; j += NTHR) {
                float kj = g_k[j], vj = g_v[j], rp = g_r[j];
                float aa = p.aa_att[lE + j], bb = p.bb_att[lE + j], pp = p.pp_att[lE + j];
                float tf = p.tf[lE + j],     td = p.td[lE + j];
                float ww = tf + kj;
                float q  = fmaxf(pp, ww);
                float e1 = expf(pp - q), e2 = expf(ww - q);
                float av = e1 * aa + e2 * vj;
                float bv = e1 * bb + e2;
                float rr = sigmoidf_(rp);
                oin[j] = rr * av / bv;
                if (blockIdx.x == 0) {
                    float ww2 = pp + td;
                    float q2  = fmaxf(ww2, kj);
                    float f1  = expf(ww2 - q2), f2 = expf(kj - q2);
                    o_aa[lE + j] = f1 * aa + f2 * vj;
                    o_bb[lE + j] = f1 * bb + f2;
                    o_pp[lE + j] = q2;
                    o_da[lE + j] = rp;
                    o_db[lE + j] = rr;
                }
            }
            __syncthreads();
            if (gw < E) {
                float s = dot8_pf(a, oin, lane);
                if (lane == 0) g_x[gw] += s;
            }
            pf8(p.Fk + lHE + (size_t)gw * E, lane, a);   // phase-C row 1
        }
        grid_sync();

        // ================= Phase C: LN2 + mixes + Fk/Fr GEMVs ==============
        {
            // early demand-issue for round 2 (Fk row if < HID, else Fr row)
            const int row2 = gw + GWARPS;                // 2368..4735
            float4 b2[8];
            pf8((row2 < HID) ? p.Fk + lHE + (size_t)row2 * E
                             : p.Fr + lEE + (size_t)(row2 - HID) * E, lane, b2);

            float* xn2 = sh; float* fxk = sh + E; float* fxr = sh + 2 * E;
            block_ln(g_x, p.ln2_w + lE, p.ln2_b + lE, xn2, red);
            for (int j = tid; j < E; j += NTHR) {
                float v = xn2[j], sxf = p.xx_ffn[lE + j];
                float ak = p.fmk[lE + j], br = p.fmr[lE + j];
                fxk[j] = v * ak + sxf * (1.f - ak);
                fxr[j] = v * br + sxf * (1.f - br);
                if (blockIdx.x == 0) o_xxf[lE + j] = v;
            }
            __syncthreads();
            {
                float s = dot8_pf(a, fxk, lane);
                s = fmaxf(s, 0.f);
                if (lane == 0) g_kf[gw] = s * s;
            }
            // round 3 exists only for gw < 384 (rows 4736..5119 — all Fr)
            const bool has3 = (gw < HID + E - 2 * GWARPS);
            if (has3)
                pf8(p.Fr + lEE + (size_t)(gw + 2 * GWARPS - HID) * E, lane, a);
            {
                float s = dot8_pf(b2, (row2 < HID) ? fxk : fxr, lane);
                if (lane == 0) {
                    if (row2 < HID) { s = fmaxf(s, 0.f); g_kf[row2] = s * s; }
                    else            g_rf[row2 - HID] = sigmoidf_(s);
                }
            }
            if (has3) {
                float s = dot8_pf(a, fxr, lane);
                if (lane == 0) g_rf[gw + 2 * GWARPS - HID] = sigmoidf_(s);
            }
            if (gw < E) pf8(p.Fv + lEH + (size_t)gw * HID, lane, a);  // D chunk0
        }
        grid_sync();

        // ================= Phase D: Fv GEMV + residual add =================
        {
            const float* Wrow = p.Fv + lEH + (size_t)gw * HID;
            float4 b2[8];
            if (gw < E) pf8(Wrow + 1024, lane, b2);      // chunk1 early issue
            {
                const float4* kf4 = (const float4*)g_kf;
                float4* sh4 = (float4*)sh;
                for (int j = tid; j < HID / 4; j += NTHR) sh4[j] = kf4[j];
            }
            __syncthreads();
            if (gw < E) {
                float s = dot8_acc(a, sh, lane, 0.f);          // chunk0
                pf8(Wrow + 2048, lane, a);                     // chunk2
                s = dot8_acc(b2, sh + 1024, lane, s);          // chunk1
                pf8(Wrow + 3072, lane, b2);                    // chunk3
                s = dot8_acc(a, sh + 2048, lane, s);           // chunk2
                s = dot8_acc(b2, sh + 3072, lane, s);          // chunk3
                s = red32(s);
                if (lane == 0) g_x[gw] += g_rf[gw] * s;
            }
            if (l + 1 < LAY) pf8(wrowA(p, l + 1, gw), lane, a);
            else             pf8(p.head_w + (size_t)gw * E, lane, a);
        }
        grid_sync();
    }

    // ================= head: LN + [V,E] GEMV (ping-pong) ===================
    block_ln(g_x, p.lno_w, p.lno_b, sh, red);
    {
        float4 b[8];
        int row = gw;
        if (row + GWARPS < VOCAB) pf8(p.head_w + (size_t)(row + GWARPS) * E, lane, b);
        while (true) {
            float s = dot8_pf(a, sh, lane);
            if (lane == 0) outv[row] = s;
            int rn = row + GWARPS;
            if (rn >= VOCAB) break;
            int rp = row + 2 * GWARPS;
            if (rp < VOCAB) pf8(p.head_w + (size_t)rp * E, lane, a);
            s = dot8_pf(b, sh, lane);
            if (lane == 0) outv[rn] = s;
            row = rp;
            if (row >= VOCAB) break;
            int rq = rn + 2 * GWARPS;
            if (rq < VOCAB) pf8(p.head_w + (size_t)rq * E, lane, b);
        }
    }
}

extern "C" void kernel_launch(void* const* d_in, const int* in_sizes, int n_in,
                              void* d_out, int out_size) {
    Params p;
    p.ctx    = (const int*)  d_in[0];
    p.xx_att = (const float*)d_in[1];
    p.aa_att = (const float*)d_in[2];
    p.bb_att = (const float*)d_in[3];
    p.pp_att = (const float*)d_in[4];
    p.xx_ffn = (const float*)d_in[5];
    p.emb_w  = (const float*)d_in[6];
    p.head_w = (const float*)d_in[7];
    p.ln0_w  = (const float*)d_in[8];
    p.ln0_b  = (const float*)d_in[9];
    p.ln1_w  = (const float*)d_in[10];
    p.ln1_b  = (const float*)d_in[11];
    p.ln2_w  = (const float*)d_in[12];
    p.ln2_b  = (const float*)d_in[13];
    p.lno_w  = (const float*)d_in[14];
    p.lno_b  = (const float*)d_in[15];
    p.mk     = (const float*)d_in[16];
    p.mv     = (const float*)d_in[17];
    p.mr     = (const float*)d_in[18];
    p.tf     = (const float*)d_in[19];
    p.td     = (const float*)d_in[20];
    p.Wr     = (const float*)d_in[21];
    p.Wk     = (const float*)d_in[22];
    p.Wv     = (const float*)d_in[23];
    p.Wo     = (const float*)d_in[24];
    p.fmk    = (const float*)d_in[25];
    p.fmr    = (const float*)d_in[26];
    p.Fr     = (const float*)d_in[27];
    p.Fk     = (const float*)d_in[28];
    p.Fv     = (const float*)d_in[29];
    p.out    = (float*)d_out;

    rwkv_kernel<<<NBLK, NTHR>>>(p);
}

// round 9
// speedup vs baseline: 1.2344x; 1.0027x over previous
#include <cuda_runtime.h>

#define E     1024
#define LAY   24
#define HID   4096
#define VOCAB 50277
#define NBLK  148
#define NTHR  512
#define NWARP (NTHR / 32)
#define GWARPS (NBLK * NWARP)   // 2368

// ---------------- scratch (device globals: no allocations allowed) ----------
__device__ __align__(16) float g_x[E];
__device__ __align__(16) float g_r[E];
__device__ __align__(16) float g_k[E];
__device__ __align__(16) float g_v[E];
__device__ __align__(16) float g_rf[E];
__device__ __align__(16) float g_kf[HID];
__device__ unsigned g_bar_leaf[8] = {0,0,0,0,0,0,0,0};
__device__ unsigned g_bar_root = 0;
__device__ volatile unsigned g_bar_gen = 0;

struct Params {
    const int*   ctx;
    const float *xx_att, *aa_att, *bb_att, *pp_att, *xx_ffn;
    const float *emb_w, *head_w;
    const float *ln0_w, *ln0_b, *ln1_w, *ln1_b, *ln2_w, *ln2_b, *lno_w, *lno_b;
    const float *mk, *mv, *mr, *tf, *td;
    const float *Wr, *Wk, *Wv, *Wo;
    const float *fmk, *fmr, *Fr, *Fk, *Fv;
    float* out;
};

// ------------- two-level software grid barrier (R3-proven version) ----------
__device__ __forceinline__ void grid_sync() {
    __syncthreads();
    if (threadIdx.x == 0) {
        const unsigned gen = g_bar_gen;
        const int b = blockIdx.x & 7;
        const unsigned cnt = 18u + (b < 4 ? 1u : 0u);   // 148 = 4*19 + 4*18
        __threadfence();
        if (atomicAdd(&g_bar_leaf[b], 1u) == cnt - 1u) {
            atomicExch(&g_bar_leaf[b], 0u);
            if (atomicAdd(&g_bar_root, 1u) == 7u) {
                atomicExch(&g_bar_root, 0u);
                __threadfence();
                g_bar_gen = gen + 1u;
            } else {
                while (g_bar_gen == gen) { __nanosleep(32); }
            }
        } else {
            while (g_bar_gen == gen) { __nanosleep(32); }
        }
        __threadfence();
    }
    __syncthreads();
}

// ---------------- block reduction (sum, broadcast) ---------------------------
__device__ __forceinline__ float block_sum(float v, float* red) {
    #pragma unroll
    for (int o = 16; o; o >>= 1) v += __shfl_xor_sync(0xffffffffu, v, o);
    int w = threadIdx.x >> 5;
    if ((threadIdx.x & 31) == 0) red[w] = v;
    __syncthreads();
    if (threadIdx.x < 32) {
        float t = (threadIdx.x < NWARP) ? red[threadIdx.x] : 0.f;
        #pragma unroll
        for (int o = 16; o; o >>= 1) t += __shfl_xor_sync(0xffffffffu, t, o);
        if (threadIdx.x == 0) red[0] = t;
    }
    __syncthreads();
    float r = red[0];
    __syncthreads();
    return r;
}

// two-pass LayerNorm: src (global) -> dst (shared), per-block redundant
__device__ void block_ln(const float* __restrict__ src,
                         const float* __restrict__ w,
                         const float* __restrict__ b,
                         float* dst, float* red) {
    float s = 0.f;
    for (int j = threadIdx.x; j < E; j += NTHR) { float t = src[j]; dst[j] = t; s += t; }
    float mean = block_sum(s, red) * (1.f / E);
    float s2 = 0.f;
    for (int j = threadIdx.x; j < E; j += NTHR) { float c = dst[j] - mean; s2 += c * c; }
    float inv = rsqrtf(block_sum(s2, red) * (1.f / E) + 1e-5f);
    for (int j = threadIdx.x; j < E; j += NTHR)
        dst[j] = (dst[j] - mean) * inv * w[j] + b[j];
    __syncthreads();
}

// ---------------- GEMV pieces ------------------------------------------------
__device__ __forceinline__ float red32(float s) {
    #pragma unroll
    for (int o = 16; o; o >>= 1) s += __shfl_xor_sync(0xffffffffu, s, o);
    return s;
}

__device__ __forceinline__ void pf8(const float* __restrict__ Wrow, int lane,
                                    float4 (&a)[8]) {
    const float4* W = (const float4*)Wrow;
    #pragma unroll
    for (int t = 0; t < 8; t++) a[t] = W[lane + 32 * t];
}

// partial dot (no reduce) — for multi-chunk accumulation
__device__ __forceinline__ float dot8_acc(const float4 (&a)[8],
                                          const float* __restrict__ vec,
                                          int lane, float s) {
    const float4* v = (const float4*)vec;
    #pragma unroll
    for (int t = 0; t < 8; t++) {
        float4 x = v[lane + 32 * t];
        s = fmaf(a[t].x, x.x, s); s = fmaf(a[t].y, x.y, s);
        s = fmaf(a[t].z, x.z, s); s = fmaf(a[t].w, x.w, s);
    }
    return s;
}

__device__ __forceinline__ float dot8_pf(const float4 (&a)[8],
                                         const float* __restrict__ vec, int lane) {
    return red32(dot8_acc(a, vec, lane, 0.f));
}

__device__ __forceinline__ float sigmoidf_(float x) {
    return 1.f / (1.f + expf(-x));
}

__device__ __forceinline__ const float* wrowA(const Params& p, int l, int row) {
    int m = row >> 10, i = row & (E - 1);
    const float* Wb = (m == 0) ? p.Wr : (m == 1) ? p.Wk : p.Wv;
    return Wb + (size_t)l * E * E + (size_t)i * E;
}

// ---------------- the whole network in one persistent kernel ----------------
__global__ void __launch_bounds__(NTHR, 1) rwkv_kernel(Params p) {
    __shared__ __align__(16) float sh[HID];   // 16KB, aliased per phase
    __shared__ float red[NWARP];

    const int tid  = threadIdx.x;
    const int gw   = blockIdx.x * NWARP + (tid >> 5);
    const int lane = tid & 31;

    float* outv  = p.out;                 // logits [V]
    float* o_xx  = p.out + VOCAB;         // xx_att_r [L,E]
    float* o_aa  = o_xx  + LAY * E;
    float* o_bb  = o_aa  + LAY * E;
    float* o_pp  = o_bb  + LAY * E;
    float* o_xxf = o_pp  + LAY * E;
    float* o_da  = o_xxf + LAY * E;       // r_pre
    float* o_db  = o_da  + LAY * E;       // sigmoid(r_pre)

    float4 a[8];                          // persistent cross-barrier buffer

    // ---- init: x0 = LN(emb[ctx], ln0) ----
    {
        int tok = p.ctx[0];
        block_ln(p.emb_w + (size_t)tok * E, p.ln0_w, p.ln0_b, sh, red);
        if (blockIdx.x == 0)
            for (int j = tid; j < E; j += NTHR) g_x[j] = sh[j];
    }
    pf8(wrowA(p, 0, gw), lane, a);
    grid_sync();

    for (int l = 0; l < LAY; l++) {
        const size_t lE  = (size_t)l * E;
        const size_t lEE = (size_t)l * E * E;
        const size_t lHE = (size_t)l * HID * E;
        const size_t lEH = (size_t)l * E * HID;

        // ================= Phase A: LN1 + mixes + r/k/v GEMVs ==============
        {
            // early demand-issue for round 2 (rows 2368..3071 — all Wv)
            const bool hasA2 = (gw < 3 * E - GWARPS);   // gw < 704
            float4 b2[8];
            if (hasA2)
                pf8(p.Wv + lEE + (size_t)(gw + GWARPS - 2048) * E, lane, b2);

            float* xn = sh; float* xk = sh + E; float* xv = sh + 2 * E; float* xr = sh + 3 * E;
            block_ln(g_x, p.ln1_w + lE, p.ln1_b + lE, xn, red);
            for (int j = tid; j < E; j += NTHR) {
                float xnj = xn[j], sx = p.xx_att[lE + j];
                float ak = p.mk[lE + j], bv = p.mv[lE + j], cr = p.mr[lE + j];
                xk[j] = xnj * ak + sx * (1.f - ak);
                xv[j] = xnj * bv + sx * (1.f - bv);
                xr[j] = xnj * cr + sx * (1.f - cr);
                if (blockIdx.x == 0) o_xx[lE + j] = xnj;
            }
            __syncthreads();
            {
                int m = gw >> 10, i = gw & (E - 1);
                const float* vec = (m == 0) ? xr : (m == 1) ? xk : xv;
                float s = dot8_pf(a, vec, lane);
                if (lane == 0) ((m == 0) ? g_r : (m == 1) ? g_k : g_v)[i] = s;
            }
            if (hasA2) {
                float s = dot8_pf(b2, xv, lane);
                if (lane == 0) g_v[gw + GWARPS - 2048] = s;
            }
            if (gw < E) pf8(p.Wo + lEE + (size_t)gw * E, lane, a);
        }
        grid_sync();

        // ================= Phase B: WKV elementwise + Wo GEMV ==============
        {
            float* oin = sh;
            for (int j = tid; j < E; j += NTHR) {
                float kj = g_k[j], vj = g_v[j], rp = g_r[j];
                float aa = p.aa_att[lE + j], bb = p.bb_att[lE + j], pp = p.pp_att[lE + j];
                float tf = p.tf[lE + j],     td = p.td[lE + j];
                float ww = tf + kj;
                float q  = fmaxf(pp, ww);
                float e1 = expf(pp - q), e2 = expf(ww - q);
                float av = e1 * aa + e2 * vj;
                float bv = e1 * bb + e2;
                float rr = sigmoidf_(rp);
                oin[j] = rr * av / bv;
                if (blockIdx.x == 0) {
                    float ww2 = pp + td;
                    float q2  = fmaxf(ww2, kj);
                    float f1  = expf(ww2 - q2), f2 = expf(kj - q2);
                    o_aa[lE + j] = f1 * aa + f2 * vj;
                    o_bb[lE + j] = f1 * bb + f2;
                    o_pp[lE + j] = q2;
                    o_da[lE + j] = rp;
                    o_db[lE + j] = rr;
                }
            }
            __syncthreads();
            if (gw < E) {
                float s = dot8_pf(a, oin, lane);
                if (lane == 0) g_x[gw] += s;
            }
            pf8(p.Fk + lHE + (size_t)gw * E, lane, a);   // phase-C row 1
        }
        grid_sync();

        // ================= Phase C: LN2 + mixes + Fk/Fr GEMVs ==============
        {
            // early demand-issue for round 2 (Fk row if < HID, else Fr row)
            const int row2 = gw + GWARPS;                // 2368..4735
            float4 b2[8];
            pf8((row2 < HID) ? p.Fk + lHE + (size_t)row2 * E
                             : p.Fr + lEE + (size_t)(row2 - HID) * E, lane, b2);

            float* xn2 = sh; float* fxk = sh + E; float* fxr = sh + 2 * E;
            block_ln(g_x, p.ln2_w + lE, p.ln2_b + lE, xn2, red);
            for (int j = tid; j < E; j += NTHR) {
                float v = xn2[j], sxf = p.xx_ffn[lE + j];
                float ak = p.fmk[lE + j], br = p.fmr[lE + j];
                fxk[j] = v * ak + sxf * (1.f - ak);
                fxr[j] = v * br + sxf * (1.f - br);
                if (blockIdx.x == 0) o_xxf[lE + j] = v;
            }
            __syncthreads();
            {
                float s = dot8_pf(a, fxk, lane);
                s = fmaxf(s, 0.f);
                if (lane == 0) g_kf[gw] = s * s;
            }
            // round 3 exists only for gw < 384 (rows 4736..5119 — all Fr)
            const bool has3 = (gw < HID + E - 2 * GWARPS);
            if (has3)
                pf8(p.Fr + lEE + (size_t)(gw + 2 * GWARPS - HID) * E, lane, a);
            {
                float s = dot8_pf(b2, (row2 < HID) ? fxk : fxr, lane);
                if (lane == 0) {
                    if (row2 < HID) { s = fmaxf(s, 0.f); g_kf[row2] = s * s; }
                    else            g_rf[row2 - HID] = sigmoidf_(s);
                }
            }
            if (has3) {
                float s = dot8_pf(a, fxr, lane);
                if (lane == 0) g_rf[gw + 2 * GWARPS - HID] = sigmoidf_(s);
            }
            if (gw < E) pf8(p.Fv + lEH + (size_t)gw * HID, lane, a);  // D chunk0
        }
        grid_sync();

        // ================= Phase D: Fv GEMV + residual add =================
        {
            const float* Wrow = p.Fv + lEH + (size_t)gw * HID;
            float4 b2[8];
            if (gw < E) pf8(Wrow + 1024, lane, b2);      // chunk1 early issue
            {
                const float4* kf4 = (const float4*)g_kf;
                float4* sh4 = (float4*)sh;
                for (int j = tid; j < HID / 4; j += NTHR) sh4[j] = kf4[j];
            }
            __syncthreads();
            if (gw < E) {
                float s = dot8_acc(a, sh, lane, 0.f);          // chunk0
                pf8(Wrow + 2048, lane, a);                     // chunk2
                s = dot8_acc(b2, sh + 1024, lane, s);          // chunk1
                pf8(Wrow + 3072, lane, b2);                    // chunk3
                s = dot8_acc(a, sh + 2048, lane, s);           // chunk2
                s = dot8_acc(b2, sh + 3072, lane, s);          // chunk3
                s = red32(s);
                if (lane == 0) g_x[gw] += g_rf[gw] * s;
            }
            if (l + 1 < LAY) pf8(wrowA(p, l + 1, gw), lane, a);
            else             pf8(p.head_w + (size_t)gw * E, lane, a);
        }
        grid_sync();
    }

    // ================= head: LN + [V,E] GEMV (ping-pong) ===================
    block_ln(g_x, p.lno_w, p.lno_b, sh, red);
    {
        float4 b[8];
        int row = gw;
        if (row + GWARPS < VOCAB) pf8(p.head_w + (size_t)(row + GWARPS) * E, lane, b);
        while (true) {
            float s = dot8_pf(a, sh, lane);
            if (lane == 0) outv[row] = s;
            int rn = row + GWARPS;
            if (rn >= VOCAB) break;
            int rp = row + 2 * GWARPS;
            if (rp < VOCAB) pf8(p.head_w + (size_t)rp * E, lane, a);
            s = dot8_pf(b, sh, lane);
            if (lane == 0) outv[rn] = s;
            row = rp;
            if (row >= VOCAB) break;
            int rq = rn + 2 * GWARPS;
            if (rq < VOCAB) pf8(p.head_w + (size_t)rq * E, lane, b);
        }
    }
}

extern "C" void kernel_launch(void* const* d_in, const int* in_sizes, int n_in,
                              void* d_out, int out_size) {
    Params p;
    p.ctx    = (const int*)  d_in[0];
    p.xx_att = (const float*)d_in[1];
    p.aa_att = (const float*)d_in[2];
    p.bb_att = (const float*)d_in[3];
    p.pp_att = (const float*)d_in[4];
    p.xx_ffn = (const float*)d_in[5];
    p.emb_w  = (const float*)d_in[6];
    p.head_w = (const float*)d_in[7];
    p.ln0_w  = (const float*)d_in[8];
    p.ln0_b  = (const float*)d_in[9];
    p.ln1_w  = (const float*)d_in[10];
    p.ln1_b  = (const float*)d_in[11];
    p.ln2_w  = (const float*)d_in[12];
    p.ln2_b  = (const float*)d_in[13];
    p.lno_w  = (const float*)d_in[14];
    p.lno_b  = (const float*)d_in[15];
    p.mk     = (const float*)d_in[16];
    p.mv     = (const float*)d_in[17];
    p.mr     = (const float*)d_in[18];
    p.tf     = (const float*)d_in[19];
    p.td     = (const float*)d_in[20];
    p.Wr     = (const float*)d_in[21];
    p.Wk     = (const float*)d_in[22];
    p.Wv     = (const float*)d_in[23];
    p.Wo     = (const float*)d_in[24];
    p.fmk    = (const float*)d_in[25];
    p.fmr    = (const float*)d_in[26];
    p.Fr     = (const float*)d_in[27];
    p.Fk     = (const float*)d_in[28];
    p.Fv     = (const float*)d_in[29];
    p.out    = (float*)d_out;

    rwkv_kernel<<<NBLK, NTHR>>>(p);
}

// round 11
// speedup vs baseline: 1.3154x; 1.0657x over previous
#include <cuda_runtime.h>

#define E     1024
#define LAY   24
#define HID   4096
#define VOCAB 50277
#define NBLK  148
#define NTHR  512
#define NWARP (NTHR / 32)
#define GWARPS (NBLK * NWARP)   // 2368

// ---------------- scratch (device globals: no allocations allowed) ----------
__device__ __align__(16) float g_x[E];
__device__ __align__(16) float g_r[E];
__device__ __align__(16) float g_k[E];
__device__ __align__(16) float g_v[E];
__device__ __align__(16) float g_rf[E];
__device__ __align__(16) float g_kf[HID];
__device__ unsigned g_bar_leaf[8] = {0,0,0,0,0,0,0,0};
__device__ unsigned g_bar_root = 0;
__device__ volatile unsigned g_bar_gen = 0;

struct Params {
    const int*   ctx;
    const float *xx_att, *aa_att, *bb_att, *pp_att, *xx_ffn;
    const float *emb_w, *head_w;
    const float *ln0_w, *ln0_b, *ln1_w, *ln1_b, *ln2_w, *ln2_b, *lno_w, *lno_b;
    const float *mk, *mv, *mr, *tf, *td;
    const float *Wr, *Wk, *Wv, *Wo;
    const float *fmk, *fmr, *Fr, *Fk, *Fv;
    float* out;
};

// ------------- two-level software grid barrier (R3-proven version) ----------
__device__ __forceinline__ void grid_sync() {
    __syncthreads();
    if (threadIdx.x == 0) {
        const unsigned gen = g_bar_gen;
        const int b = blockIdx.x & 7;
        const unsigned cnt = 18u + (b < 4 ? 1u : 0u);   // 148 = 4*19 + 4*18
        __threadfence();
        if (atomicAdd(&g_bar_leaf[b], 1u) == cnt - 1u) {
            atomicExch(&g_bar_leaf[b], 0u);
            if (atomicAdd(&g_bar_root, 1u) == 7u) {
                atomicExch(&g_bar_root, 0u);
                __threadfence();
                g_bar_gen = gen + 1u;
            } else {
                while (g_bar_gen == gen) { __nanosleep(32); }
            }
        } else {
            while (g_bar_gen == gen) { __nanosleep(32); }
        }
        __threadfence();
    }
    __syncthreads();
}

// ---------------- block reduction (sum, broadcast) ---------------------------
__device__ __forceinline__ float block_sum(float v, float* red) {
    #pragma unroll
    for (int o = 16; o; o >>= 1) v += __shfl_xor_sync(0xffffffffu, v, o);
    int w = threadIdx.x >> 5;
    if ((threadIdx.x & 31) == 0) red[w] = v;
    __syncthreads();
    if (threadIdx.x < 32) {
        float t = (threadIdx.x < NWARP) ? red[threadIdx.x] : 0.f;
        #pragma unroll
        for (int o = 16; o; o >>= 1) t += __shfl_xor_sync(0xffffffffu, t, o);
        if (threadIdx.x == 0) red[0] = t;
    }
    __syncthreads();
    float r = red[0];
    __syncthreads();
    return r;
}

// generic two-pass LN (init only)
__device__ void block_ln(const float* __restrict__ src,
                         const float* __restrict__ w,
                         const float* __restrict__ b,
                         float* dst, float* red) {
    float s = 0.f;
    for (int j = threadIdx.x; j < E; j += NTHR) { float t = src[j]; dst[j] = t; s += t; }
    float mean = block_sum(s, red) * (1.f / E);
    float s2 = 0.f;
    for (int j = threadIdx.x; j < E; j += NTHR) { float c = dst[j] - mean; s2 += c * c; }
    float inv = rsqrtf(block_sum(s2, red) * (1.f / E) + 1e-5f);
    for (int j = threadIdx.x; j < E; j += NTHR)
        dst[j] = (dst[j] - mean) * inv * w[j] + b[j];
    __syncthreads();
}

// ---------------- GEMV pieces ------------------------------------------------
__device__ __forceinline__ float red32(float s) {
    #pragma unroll
    for (int o = 16; o; o >>= 1) s += __shfl_xor_sync(0xffffffffu, s, o);
    return s;
}

__device__ __forceinline__ void pf8(const float* __restrict__ Wrow, int lane,
                                    float4 (&a)[8]) {
    const float4* W = (const float4*)Wrow;
    #pragma unroll
    for (int t = 0; t < 8; t++) a[t] = W[lane + 32 * t];
}

__device__ __forceinline__ float dot8_acc(const float4 (&a)[8],
                                          const float* __restrict__ vec,
                                          int lane, float s) {
    const float4* v = (const float4*)vec;
    #pragma unroll
    for (int t = 0; t < 8; t++) {
        float4 x = v[lane + 32 * t];
        s = fmaf(a[t].x, x.x, s); s = fmaf(a[t].y, x.y, s);
        s = fmaf(a[t].z, x.z, s); s = fmaf(a[t].w, x.w, s);
    }
    return s;
}

__device__ __forceinline__ float dot8_pf(const float4 (&a)[8],
                                         const float* __restrict__ vec, int lane) {
    return red32(dot8_acc(a, vec, lane, 0.f));
}

__device__ __forceinline__ float sigmoidf_(float x) {
    return 1.f / (1.f + expf(-x));
}

__device__ __forceinline__ const float* wrowA(const Params& p, int l, int row) {
    int m = row >> 10, i = row & (E - 1);
    const float* Wb = (m == 0) ? p.Wr : (m == 1) ? p.Wk : p.Wv;
    return Wb + (size_t)l * E * E + (size_t)i * E;
}

// ---------------- the whole network in one persistent kernel ----------------
__global__ void __launch_bounds__(NTHR, 1) rwkv_kernel(Params p) {
    __shared__ __align__(16) float sh[HID];   // 16KB, aliased per phase
    __shared__ float red[NWARP];

    const int tid  = threadIdx.x;
    const int gw   = blockIdx.x * NWARP + (tid >> 5);
    const int lane = tid & 31;
    const int j0 = tid, j1 = tid + NTHR;      // each thread owns 2 elements

    float* outv  = p.out;
    float* o_xx  = p.out + VOCAB;
    float* o_aa  = o_xx  + LAY * E;
    float* o_bb  = o_aa  + LAY * E;
    float* o_pp  = o_bb  + LAY * E;
    float* o_xxf = o_pp  + LAY * E;
    float* o_da  = o_xxf + LAY * E;
    float* o_db  = o_da  + LAY * E;

    float4 a[8], b[8];                        // cross-barrier row buffers

    // cached next-phase params (loaded one phase ahead)
    float c_sx0, c_sx1, c_mk0, c_mk1, c_mv0, c_mv1, c_mr0, c_mr1;          // A
    float c_aa0, c_aa1, c_bb0, c_bb1, c_pp0, c_pp1, c_tf0, c_tf1, c_td0, c_td1; // B
    float c_xf0, c_xf1, c_fk0, c_fk1, c_fr0, c_fr1;                         // C

    // ---- init: x0 = LN(emb[ctx], ln0) ----
    {
        int tok = p.ctx[0];
        block_ln(p.emb_w + (size_t)tok * E, p.ln0_w, p.ln0_b, sh, red);
        if (blockIdx.x == 0)
            for (int j = tid; j < E; j += NTHR) g_x[j] = sh[j];
    }
    // A(0) params + rows before first barrier
    c_sx0 = p.xx_att[j0]; c_sx1 = p.xx_att[j1];
    c_mk0 = p.mk[j0]; c_mk1 = p.mk[j1];
    c_mv0 = p.mv[j0]; c_mv1 = p.mv[j1];
    c_mr0 = p.mr[j0]; c_mr1 = p.mr[j1];
    pf8(wrowA(p, 0, gw), lane, a);
    if (gw < 3 * E - GWARPS) pf8(wrowA(p, 0, gw + GWARPS), lane, b);
    grid_sync();

    for (int l = 0; l < LAY; l++) {
        const size_t lE  = (size_t)l * E;
        const size_t lEE = (size_t)l * E * E;
        const size_t lHE = (size_t)l * HID * E;
        const size_t lEH = (size_t)l * E * HID;
        const bool hasA2 = (gw < 3 * E - GWARPS);   // gw < 704
        const bool actB  = (gw < E);

        // ============ Phase A: inline LN1 + mixes + r/k/v GEMVs ============
        {
            float x0 = g_x[j0], x1 = g_x[j1];
            float mean = block_sum(x0 + x1, red) * (1.f / E);
            float d0 = x0 - mean, d1 = x1 - mean;
            float inv = rsqrtf(block_sum(d0 * d0 + d1 * d1, red) * (1.f / E) + 1e-5f);
            float w0 = p.ln1_w[lE + j0], w1 = p.ln1_w[lE + j1];
            float bb0 = p.ln1_b[lE + j0], bb1 = p.ln1_b[lE + j1];
            float xn0 = d0 * inv * w0 + bb0, xn1 = d1 * inv * w1 + bb1;
            // xk at sh, xv at sh+E, xr at sh+2E
            sh[j0]         = xn0 * c_mk0 + c_sx0 * (1.f - c_mk0);
            sh[j1]         = xn1 * c_mk1 + c_sx1 * (1.f - c_mk1);
            sh[E + j0]     = xn0 * c_mv0 + c_sx0 * (1.f - c_mv0);
            sh[E + j1]     = xn1 * c_mv1 + c_sx1 * (1.f - c_mv1);
            sh[2 * E + j0] = xn0 * c_mr0 + c_sx0 * (1.f - c_mr0);
            sh[2 * E + j1] = xn1 * c_mr1 + c_sx1 * (1.f - c_mr1);
            if (blockIdx.x == 0) { o_xx[lE + j0] = xn0; o_xx[lE + j1] = xn1; }
            __syncthreads();
            {
                int m = gw >> 10, i = gw & (E - 1);
                const float* vec = (m == 0) ? sh + 2 * E : (m == 1) ? sh : sh + E;
                float s = dot8_pf(a, vec, lane);
                if (lane == 0) ((m == 0) ? g_r : (m == 1) ? g_k : g_v)[i] = s;
            }
            if (hasA2) {
                float s = dot8_pf(b, sh + E, lane);       // all Wv rows
                if (lane == 0) g_v[gw + GWARPS - 2048] = s;
            }
            // prep B: actives carry Wo row; idles carry their C round-1 row
            if (actB) pf8(p.Wo + lEE + (size_t)gw * E, lane, a);
            else      pf8(p.Fk + lHE + (size_t)gw * E, lane, a);
            // B params
            c_aa0 = p.aa_att[lE + j0]; c_aa1 = p.aa_att[lE + j1];
            c_bb0 = p.bb_att[lE + j0]; c_bb1 = p.bb_att[lE + j1];
            c_pp0 = p.pp_att[lE + j0]; c_pp1 = p.pp_att[lE + j1];
            c_tf0 = p.tf[lE + j0];     c_tf1 = p.tf[lE + j1];
            c_td0 = p.td[lE + j0];     c_td1 = p.td[lE + j1];
        }
        grid_sync();

        // ============ Phase B: WKV elementwise + Wo GEMV ===================
        {
            float k0 = g_k[j0], k1 = g_k[j1];
            float v0 = g_v[j0], v1 = g_v[j1];
            float r0 = g_r[j0], r1 = g_r[j1];
            float ww0 = c_tf0 + k0, ww1 = c_tf1 + k1;
            float q0 = fmaxf(c_pp0, ww0), q1 = fmaxf(c_pp1, ww1);
            float e10 = expf(c_pp0 - q0), e20 = expf(ww0 - q0);
            float e11 = expf(c_pp1 - q1), e21 = expf(ww1 - q1);
            float rr0 = sigmoidf_(r0), rr1 = sigmoidf_(r1);
            sh[j0] = rr0 * (e10 * c_aa0 + e20 * v0) / (e10 * c_bb0 + e20);
            sh[j1] = rr1 * (e11 * c_aa1 + e21 * v1) / (e11 * c_bb1 + e21);
            if (blockIdx.x == 0) {
                float w20 = c_pp0 + c_td0, w21 = c_pp1 + c_td1;
                float q20 = fmaxf(w20, k0), q21 = fmaxf(w21, k1);
                float f10 = expf(w20 - q20), f20 = expf(k0 - q20);
                float f11 = expf(w21 - q21), f21 = expf(k1 - q21);
                o_aa[lE + j0] = f10 * c_aa0 + f20 * v0;
                o_aa[lE + j1] = f11 * c_aa1 + f21 * v1;
                o_bb[lE + j0] = f10 * c_bb0 + f20;
                o_bb[lE + j1] = f11 * c_bb1 + f21;
                o_pp[lE + j0] = q20; o_pp[lE + j1] = q21;
                o_da[lE + j0] = r0;  o_da[lE + j1] = r1;
                o_db[lE + j0] = rr0; o_db[lE + j1] = rr1;
            }
            __syncthreads();
            if (actB) {
                float s = dot8_pf(a, sh, lane);
                if (lane == 0) g_x[gw] += s;
                pf8(p.Fk + lHE + (size_t)gw * E, lane, a);   // C round-1
            }
            {   // C round-2 row for everyone
                int row2 = gw + GWARPS;
                pf8((row2 < HID) ? p.Fk + lHE + (size_t)row2 * E
                                 : p.Fr + lEE + (size_t)(row2 - HID) * E, lane, b);
            }
            // C params
            c_xf0 = p.xx_ffn[lE + j0]; c_xf1 = p.xx_ffn[lE + j1];
            c_fk0 = p.fmk[lE + j0];    c_fk1 = p.fmk[lE + j1];
            c_fr0 = p.fmr[lE + j0];    c_fr1 = p.fmr[lE + j1];
        }
        grid_sync();

        // ============ Phase C: inline LN2 + mixes + Fk/Fr GEMVs ============
        {
            float x0 = g_x[j0], x1 = g_x[j1];
            float mean = block_sum(x0 + x1, red) * (1.f / E);
            float d0 = x0 - mean, d1 = x1 - mean;
            float inv = rsqrtf(block_sum(d0 * d0 + d1 * d1, red) * (1.f / E) + 1e-5f);
            float w0 = p.ln2_w[lE + j0], w1 = p.ln2_w[lE + j1];
            float bb0 = p.ln2_b[lE + j0], bb1 = p.ln2_b[lE + j1];
            float xn0 = d0 * inv * w0 + bb0, xn1 = d1 * inv * w1 + bb1;
            sh[j0]     = xn0 * c_fk0 + c_xf0 * (1.f - c_fk0);   // fxk
            sh[j1]     = xn1 * c_fk1 + c_xf1 * (1.f - c_fk1);
            sh[E + j0] = xn0 * c_fr0 + c_xf0 * (1.f - c_fr0);   // fxr
            sh[E + j1] = xn1 * c_fr1 + c_xf1 * (1.f - c_fr1);
            if (blockIdx.x == 0) { o_xxf[lE + j0] = xn0; o_xxf[lE + j1] = xn1; }
            __syncthreads();
            {
                float s = dot8_pf(a, sh, lane);
                s = fmaxf(s, 0.f);
                if (lane == 0) g_kf[gw] = s * s;
            }
            const bool has3 = (gw < HID + E - 2 * GWARPS);     // gw < 384
            if (has3) pf8(p.Fr + lEE + (size_t)(gw + 2 * GWARPS - HID) * E, lane, a);
            {
                int row2 = gw + GWARPS;
                float s = dot8_pf(b, (row2 < HID) ? sh : sh + E, lane);
                if (lane == 0) {
                    if (row2 < HID) { s = fmaxf(s, 0.f); g_kf[row2] = s * s; }
                    else            g_rf[row2 - HID] = sigmoidf_(s);
                }
            }
            if (has3) {
                float s = dot8_pf(a, sh + E, lane);
                if (lane == 0) g_rf[gw + 2 * GWARPS - HID] = sigmoidf_(s);
            }
            // prep D: actives carry Fv chunks 0+1; idles carry next A / head row
            if (actB) {
                pf8(p.Fv + lEH + (size_t)gw * HID, lane, a);
                pf8(p.Fv + lEH + (size_t)gw * HID + 1024, lane, b);
            } else {
                if (l + 1 < LAY) pf8(wrowA(p, l + 1, gw), lane, a);
                else             pf8(p.head_w + (size_t)gw * E, lane, a);
            }
        }
        grid_sync();

        // ============ Phase D: Fv GEMV + residual add ======================
        {
            {
                const float4* kf4 = (const float4*)g_kf;
                float4* sh4 = (float4*)sh;
                #pragma unroll
                for (int j = tid; j < HID / 4; j += NTHR) sh4[j] = kf4[j];
            }
            __syncthreads();
            if (actB) {
                const float* Wrow = p.Fv + lEH + (size_t)gw * HID;
                float s = dot8_acc(a, sh, lane, 0.f);          // chunk0
                pf8(Wrow + 2048, lane, a);                     // chunk2
                s = dot8_acc(b, sh + 1024, lane, s);           // chunk1
                pf8(Wrow + 3072, lane, b);                     // chunk3
                s = dot8_acc(a, sh + 2048, lane, s);
                s = dot8_acc(b, sh + 3072, lane, s);
                s = red32(s);
                if (lane == 0) g_x[gw] += g_rf[gw] * s;
                // reload next-phase rows (idles already hold theirs from C)
                if (l + 1 < LAY) {
                    pf8(wrowA(p, l + 1, gw), lane, a);
                    if (hasA2) pf8(wrowA(p, l + 1, gw + GWARPS), lane, b);
                } else {
                    pf8(p.head_w + (size_t)gw * E, lane, a);
                }
            } else if (hasA2) {
                // (never taken: hasA2 implies gw<704<1024=actB) — kept for clarity
            }
            // next A params / final-LN params
            if (l + 1 < LAY) {
                const size_t nE = lE + E;
                c_sx0 = p.xx_att[nE + j0]; c_sx1 = p.xx_att[nE + j1];
                c_mk0 = p.mk[nE + j0]; c_mk1 = p.mk[nE + j1];
                c_mv0 = p.mv[nE + j0]; c_mv1 = p.mv[nE + j1];
                c_mr0 = p.mr[nE + j0]; c_mr1 = p.mr[nE + j1];
            } else {
                c_sx0 = p.lno_w[j0]; c_sx1 = p.lno_w[j1];    // reuse regs: w
                c_mk0 = p.lno_b[j0]; c_mk1 = p.lno_b[j1];    // reuse regs: b
            }
        }
        grid_sync();
    }

    // ================= head: inline final LN + [V,E] GEMV ==================
    {
        float x0 = g_x[j0], x1 = g_x[j1];
        float mean = block_sum(x0 + x1, red) * (1.f / E);
        float d0 = x0 - mean, d1 = x1 - mean;
        float inv = rsqrtf(block_sum(d0 * d0 + d1 * d1, red) * (1.f / E) + 1e-5f);
        sh[j0] = d0 * inv * c_sx0 + c_mk0;
        sh[j1] = d1 * inv * c_sx1 + c_mk1;
        __syncthreads();
    }
    {
        int row = gw;
        if (row + GWARPS < VOCAB) pf8(p.head_w + (size_t)(row + GWARPS) * E, lane, b);
        while (true) {
            float s = dot8_pf(a, sh, lane);
            if (lane == 0) outv[row] = s;
            int rn = row + GWARPS;
            if (rn >= VOCAB) break;
            int rp = row + 2 * GWARPS;
            if (rp < VOCAB) pf8(p.head_w + (size_t)rp * E, lane, a);
            s = dot8_pf(b, sh, lane);
            if (lane == 0) outv[rn] = s;
            row = rp;
            if (row >= VOCAB) break;
            int rq = rn + 2 * GWARPS;
            if (rq < VOCAB) pf8(p.head_w + (size_t)rq * E, lane, b);
        }
    }
}

extern "C" void kernel_launch(void* const* d_in, const int* in_sizes, int n_in,
                              void* d_out, int out_size) {
    Params p;
    p.ctx    = (const int*)  d_in[0];
    p.xx_att = (const float*)d_in[1];
    p.aa_att = (const float*)d_in[2];
    p.bb_att = (const float*)d_in[3];
    p.pp_att = (const float*)d_in[4];
    p.xx_ffn = (const float*)d_in[5];
    p.emb_w  = (const float*)d_in[6];
    p.head_w = (const float*)d_in[7];
    p.ln0_w  = (const float*)d_in[8];
    p.ln0_b  = (const float*)d_in[9];
    p.ln1_w  = (const float*)d_in[10];
    p.ln1_b  = (const float*)d_in[11];
    p.ln2_w  = (const float*)d_in[12];
    p.ln2_b  = (const float*)d_in[13];
    p.lno_w  = (const float*)d_in[14];
    p.lno_b  = (const float*)d_in[15];
    p.mk     = (const float*)d_in[16];
    p.mv     = (const float*)d_in[17];
    p.mr     = (const float*)d_in[18];
    p.tf     = (const float*)d_in[19];
    p.td     = (const float*)d_in[20];
    p.Wr     = (const float*)d_in[21];
    p.Wk     = (const float*)d_in[22];
    p.Wv     = (const float*)d_in[23];
    p.Wo     = (const float*)d_in[24];
    p.fmk    = (const float*)d_in[25];
    p.fmr    = (const float*)d_in[26];
    p.Fr     = (const float*)d_in[27];
    p.Fk     = (const float*)d_in[28];
    p.Fv     = (const float*)d_in[29];
    p.out    = (float*)d_out;

    rwkv_kernel<<<NBLK, NTHR>>>(p);
}